// round 12
// baseline (speedup 1.0000x reference)
#include <cuda_runtime.h>
#include <cuda_fp16.h>
#include <math.h>
#include <stdint.h>

// Problem constants
#define BATCH 64
#define SEG   8
#define CIN   256
#define RNK   64
#define HWSZ  196      // 14*14
#define P1    169      // 13*13
#define M1    10816    // BATCH * P1
#define M1P   10880    // padded to 85*128

// ---------------- scratch ----------------
__device__ float  g_awin[BATCH * 2048];            // conv1 window sums
__device__ float  g_att_acc[BATCH * 512];          // conv2-mean accumulator
__device__ float  g_xr[BATCH * RNK * SEG * HWSZ];  // raw rank GEMM [b][r][s][hw]
__device__ __half g_w1h[512 * 1024];               // pre-split conv1 weights (hi)
__device__ __half g_w1l[512 * 1024];               // pre-split conv1 weights (lo)
__device__ __half g_rwh[SEG * RNK * CIN];          // pre-split rank weights (hi)
__device__ __half g_rwl[SEG * RNK * CIN];          // pre-split rank weights (lo)
__device__ __half g_a1h[(size_t)1024 * M1P];       // pre-split im2col A (hi) [k][m]
__device__ __half g_a1l[(size_t)1024 * M1P];       // pre-split im2col A (lo) [k][m]

// ---------------- helpers ----------------
__device__ __forceinline__ uint32_t smem_u32(const void* p) {
    uint32_t a;
    asm("{ .reg .u64 t; cvta.to.shared.u64 t, %1; cvt.u32.u64 %0, t; }"
        : "=r"(a) : "l"(p));
    return a;
}

__device__ __forceinline__ void mma_f16(float* d, const uint32_t* a,
                                        uint32_t b0, uint32_t b1) {
    asm volatile(
        "mma.sync.aligned.m16n8k16.row.col.f32.f16.f16.f32 "
        "{%0,%1,%2,%3},{%4,%5,%6,%7},{%8,%9},{%0,%1,%2,%3};"
        : "+f"(d[0]), "+f"(d[1]), "+f"(d[2]), "+f"(d[3])
        : "r"(a[0]), "r"(a[1]), "r"(a[2]), "r"(a[3]), "r"(b0), "r"(b1));
}

__device__ __forceinline__ void ldsm4(uint32_t* r, uint32_t addr) {
    asm volatile("ldmatrix.sync.aligned.m8n8.x4.shared.b16 {%0,%1,%2,%3}, [%4];"
                 : "=r"(r[0]), "=r"(r[1]), "=r"(r[2]), "=r"(r[3]) : "r"(addr));
}
__device__ __forceinline__ void ldsm4t(uint32_t* r, uint32_t addr) {
    asm volatile("ldmatrix.sync.aligned.m8n8.x4.trans.shared.b16 {%0,%1,%2,%3}, [%4];"
                 : "=r"(r[0]), "=r"(r[1]), "=r"(r[2]), "=r"(r[3]) : "r"(addr));
}

__device__ __forceinline__ void split2(float v, __half& h, __half& l) {
    h = __float2half_rn(v);
    l = __float2half_rn(v - __half2float(h));
}

// cp.async 16B global->shared (used only in k_rank; hidden under conv1)
__device__ __forceinline__ void cpa16(uint32_t dst, const void* src) {
    asm volatile("cp.async.cg.shared.global [%0], [%1], 16;"
                 :: "r"(dst), "l"(__cvta_generic_to_global(src)));
}
#define CPA_COMMIT() asm volatile("cp.async.commit_group;" ::: "memory")
#define CPA_WAIT0()  asm volatile("cp.async.wait_group 0;"  ::: "memory")

// =====================================================================
// Kernel 0: zero buffers + pre-split weights, one kernel.
// =====================================================================
__global__ void k_init(const float* __restrict__ w1,
                       const float* __restrict__ rank_w)
{
    const int blk = blockIdx.x;
    if (blk < 640) {
        const int i = blk * 256 + threadIdx.x;
        if (i < 131072) g_awin[i] = 0.f;
        else            g_att_acc[i - 131072] = 0.f;
    } else if (blk < 1152) {
        const int i = ((blk - 640) * 256 + threadIdx.x) * 4;
        const float4 v = *(const float4*)(w1 + i);
        __half h[4], l[4];
        split2(v.x, h[0], l[0]); split2(v.y, h[1], l[1]);
        split2(v.z, h[2], l[2]); split2(v.w, h[3], l[3]);
        *(uint2*)&g_w1h[i] = *(const uint2*)h;
        *(uint2*)&g_w1l[i] = *(const uint2*)l;
    } else {
        const int i = ((blk - 1152) * 256 + threadIdx.x) * 4;  // 128 blocks cover 131072
        const float4 v = *(const float4*)(rank_w + i);
        __half h[4], l[4];
        split2(v.x, h[0], l[0]); split2(v.y, h[1], l[1]);
        split2(v.z, h[2], l[2]); split2(v.w, h[3], l[3]);
        *(uint2*)&g_rwh[i] = *(const uint2*)h;
        *(uint2*)&g_rwl[i] = *(const uint2*)l;
    }
}

// =====================================================================
// Kernel 0c: pre-split im2col A into k-major fp16 hi/lo planes.
//   grid (43, 256): x covers m (0..11007, guard M1P), y = conv channel.
//   Reads m-fast (coalesced); writes [k][m] (m-contiguous, coalesced).
//   Rows m in [M1, M1P) zero-filled.
// =====================================================================
__global__ void k_prepA(const float* __restrict__ in)
{
    const int m  = blockIdx.x * 256 + threadIdx.x;
    if (m >= M1P) return;
    const int ch = blockIdx.y;

    float v0 = 0.f, v1 = 0.f, v2 = 0.f, v3 = 0.f;
    if (m < M1) {
        const int bb = m / 169, p = m % 169;
        const int yy = p / 13, xx = p % 13;
        const float* pA = in + ((size_t)(bb * 8 + (ch >> 5)) * CIN + (ch & 31)) * HWSZ
                          + yy * 14 + xx;
        v0 = pA[0]; v1 = pA[1]; v2 = pA[14]; v3 = pA[15];
    }
    __half h[4], l[4];
    split2(v0, h[0], l[0]); split2(v1, h[1], l[1]);
    split2(v2, h[2], l[2]); split2(v3, h[3], l[3]);

    const size_t base = (size_t)ch * 4 * M1P + m;
    g_a1h[base          ] = h[0];
    g_a1h[base +     M1P] = h[1];
    g_a1h[base + 2 * M1P] = h[2];
    g_a1h[base + 3 * M1P] = h[3];
    g_a1l[base          ] = l[0];
    g_a1l[base +     M1P] = l[1];
    g_a1l[base + 2 * M1P] = l[2];
    g_a1l[base + 3 * M1P] = l[3];
}

// =====================================================================
// Kernel 1: conv1 + bias + relu + fused window sums, fp16 3-pass mma
//   A pre-split k-major in global: pure uint4 copies into [k][m] smem,
//   fragmented with ldmatrix.trans (k_rank-proven pattern).
//   B pre-split via LDG.128 + STS.128 (L1-cached reuse).
// =====================================================================
#define ASTRA 136                 // A row halves (128 m + 8 pad)
#define A_PL  (16 * ASTRA)        // halves per A plane per buffer
#define A_PLB (A_PL * 2)          // bytes
#define BSTR  24                  // B row halves
#define B_PLB (128 * BSTR * 2)    // bytes per B plane per buffer

__global__ __launch_bounds__(256, 2)
void k_conv1(const float* __restrict__ b1)
{
    __shared__ __align__(16) __half sAh[2][A_PL];
    __shared__ __align__(16) __half sAl[2][A_PL];
    __shared__ __align__(16) __half sBh[2][128 * BSTR];
    __shared__ __align__(16) __half sBl[2][128 * BSTR];

    const int tid = threadIdx.x;
    const int mt  = blockIdx.x;   // 0..84
    const int nt  = blockIdx.y;   // 0..3

    // ---- A loader: thread = (krow 0..15, mseg 0..15)
    const int krow = tid >> 4;
    const int mcol = (tid & 15) * 8;
    const size_t aoff0 = (size_t)krow * M1P + mt * 128 + mcol;

    // ---- B loader: thread = (lm 0..127, lh 0..1)
    const int lm = tid & 127;
    const int lh = tid >> 7;
    const __half* w1hp = g_w1h + (size_t)(nt * 128 + lm) * 1024 + lh * 8;
    const __half* w1lp = g_w1l + (size_t)(nt * 128 + lm) * 1024 + lh * 8;

    const uint32_t stAh = smem_u32(&sAh[0][krow * ASTRA + mcol]);
    const uint32_t stAl = smem_u32(&sAl[0][krow * ASTRA + mcol]);
    const uint32_t stBh = smem_u32(&sBh[0][lm * BSTR + lh * 8]);
    const uint32_t stBl = smem_u32(&sBl[0][lm * BSTR + lh * 8]);

    const int w    = tid >> 5;
    const int lane = tid & 31;
    const int wm   = w & 3;
    const int wn   = w >> 2;
    const int am   = wm * 32;
    const int bn   = wn * 64;

    const int lr  = lane & 7;
    const int sel = lane >> 3;
    // A fragment (ldsm.trans from [k][m] smem): k-row, m-col
    const uint32_t aOff = (uint32_t)(((sel >> 1) * 8 + lr) * ASTRA) * 2u;
    // B fragment (non-trans from [n][k] smem)
    const int bRow  = (sel >> 1) * 8 + lr;
    const int bByte = (sel & 1) * 16;

    const uint32_t baseAh = smem_u32(&sAh[0][0]);
    const uint32_t baseAl = smem_u32(&sAl[0][0]);
    const uint32_t baseBh = smem_u32(&sBh[0][0]);
    const uint32_t baseBl = smem_u32(&sBl[0][0]);

    float acc[2][8][4];
#pragma unroll
    for (int i = 0; i < 2; i++)
#pragma unroll
        for (int j = 0; j < 8; j++)
#pragma unroll
            for (int c = 0; c < 4; c++) acc[i][j][c] = 0.f;

    uint4 ahv, alv, bhv, blv;

#define LOAD_REGS(ST) do {                                                \
        ahv = *(const uint4*)(g_a1h + aoff0 + (size_t)(ST) * 16 * M1P);   \
        alv = *(const uint4*)(g_a1l + aoff0 + (size_t)(ST) * 16 * M1P);   \
        bhv = *(const uint4*)(w1hp + (ST) * 16);                          \
        blv = *(const uint4*)(w1lp + (ST) * 16);                          \
    } while (0)

#define STORE_REGS(BUF) do {                                              \
        asm volatile("st.shared.v4.b32 [%0], {%1,%2,%3,%4};" ::           \
            "r"(stAh + (BUF) * A_PLB),                                    \
            "r"(ahv.x), "r"(ahv.y), "r"(ahv.z), "r"(ahv.w));              \
        asm volatile("st.shared.v4.b32 [%0], {%1,%2,%3,%4};" ::           \
            "r"(stAl + (BUF) * A_PLB),                                    \
            "r"(alv.x), "r"(alv.y), "r"(alv.z), "r"(alv.w));              \
        asm volatile("st.shared.v4.b32 [%0], {%1,%2,%3,%4};" ::           \
            "r"(stBh + (BUF) * B_PLB),                                    \
            "r"(bhv.x), "r"(bhv.y), "r"(bhv.z), "r"(bhv.w));              \
        asm volatile("st.shared.v4.b32 [%0], {%1,%2,%3,%4};" ::           \
            "r"(stBl + (BUF) * B_PLB),                                    \
            "r"(blv.x), "r"(blv.y), "r"(blv.z), "r"(blv.w));              \
    } while (0)

    LOAD_REGS(0);
    STORE_REGS(0);
    __syncthreads();

    for (int st = 0; st < 64; ++st) {
        const int cur = st & 1;
        if (st + 1 < 64) LOAD_REGS(st + 1);

        uint32_t ah[2][4], al[2][4];
#pragma unroll
        for (int i = 0; i < 2; i++) {
            const uint32_t ro = cur * A_PLB + aOff
                              + (uint32_t)(am + i * 16 + (sel & 1) * 8) * 2u;
            ldsm4t(ah[i], baseAh + ro);
            ldsm4t(al[i], baseAl + ro);
        }

#pragma unroll
        for (int jj = 0; jj < 4; ++jj) {
            const uint32_t ro = cur * B_PLB
                              + (uint32_t)((bn + jj * 16 + bRow) * BSTR) * 2u + bByte;
            uint32_t bh[4], bl[4];
            ldsm4(bh, baseBh + ro);
            ldsm4(bl, baseBl + ro);
#pragma unroll
            for (int t = 0; t < 2; ++t) {
                const int j = jj * 2 + t;
#pragma unroll
                for (int i = 0; i < 2; ++i) {
                    mma_f16(acc[i][j], ah[i], bh[t * 2], bh[t * 2 + 1]);  // hh
                    mma_f16(acc[i][j], ah[i], bl[t * 2], bl[t * 2 + 1]);  // hl
                    mma_f16(acc[i][j], al[i], bh[t * 2], bh[t * 2 + 1]);  // lh
                }
            }
        }

        if (st + 1 < 64) STORE_REGS(cur ^ 1);
        __syncthreads();
    }

    // ---- fused epilogue: bias + relu + window sums -> g_awin atomics
    const int qr = lane >> 2;
    const int qc = lane & 3;
    const int b0 = (mt * 128) / 169;
#pragma unroll
    for (int j = 0; j < 8; j++) {
        const int nbase = nt * 128 + bn + j * 8 + qc * 2;
        const float bia0 = __ldg(b1 + nbase);
        const float bia1 = __ldg(b1 + nbase + 1);
#pragma unroll
        for (int z = 0; z < 2; z++) {
            const float bia = z ? bia1 : bia0;
            float w4[2][4] = {{0.f,0.f,0.f,0.f},{0.f,0.f,0.f,0.f}};
#pragma unroll
            for (int i = 0; i < 2; i++) {
#pragma unroll
                for (int h = 0; h < 2; h++) {
                    const int mr = mt * 128 + am + i * 16 + qr + h * 8;
                    if (mr < M1) {
                        float v = acc[i][j][h * 2 + z] + bia;
                        v = v > 0.f ? v : 0.f;
                        const int bl2 = mr / 169 - b0;
                        const int pp  = mr % 169;
                        const int y   = pp / 13, x = pp - y * 13;
                        if (y < 12) { if (x < 12) w4[bl2][0] += v; if (x > 0) w4[bl2][1] += v; }
                        if (y > 0)  { if (x < 12) w4[bl2][2] += v; if (x > 0) w4[bl2][3] += v; }
                    }
                }
            }
#pragma unroll
            for (int o = 4; o <= 16; o <<= 1)
#pragma unroll
                for (int bl2 = 0; bl2 < 2; bl2++)
#pragma unroll
                    for (int t = 0; t < 4; t++)
                        w4[bl2][t] += __shfl_xor_sync(0xffffffffu, w4[bl2][t], o);
            if (qr == 0) {
                const int n = nbase + z;
#pragma unroll
                for (int bl2 = 0; bl2 < 2; bl2++) {
                    const int bg = b0 + bl2;
#pragma unroll
                    for (int t = 0; t < 4; t++)
                        if (w4[bl2][t] != 0.f)
                            atomicAdd(&g_awin[bg * 2048 + n * 4 + t], w4[bl2][t]);
                }
            }
        }
    }
#undef LOAD_REGS
#undef STORE_REGS
}

// =====================================================================
// Kernel 3: conv2-as-GEMM on window sums. M=64, N=512, K=2048.
//   K split 32 ways (chunk 64) for occupancy.
// =====================================================================
__global__ __launch_bounds__(256)
void k_gemm2(const float* __restrict__ w2)
{
    __shared__ __align__(16) float As[16][64];
    __shared__ __align__(16) float Bs[16][64];

    const int ot = blockIdx.x, ks = blockIdx.y;   // ot 0..7, ks 0..31
    const int tid = threadIdx.x;
    const int l = tid & 63, kg = tid >> 6;
    const int tm = tid >> 4, tn = tid & 15;

    float acc[4][4];
#pragma unroll
    for (int i = 0; i < 4; i++)
#pragma unroll
        for (int j = 0; j < 4; j++) acc[i][j] = 0.f;

    for (int it = 0; it < 4; ++it) {
        const int kb = ks * 64 + it * 16;
        const float4 av = *(const float4*)&g_awin[l * 2048 + kb + kg * 4];
        const float4 bv = *(const float4*)(w2 + (size_t)(ot * 64 + l) * 2048 + kb + kg * 4);
        As[kg * 4 + 0][l] = av.x; As[kg * 4 + 1][l] = av.y;
        As[kg * 4 + 2][l] = av.z; As[kg * 4 + 3][l] = av.w;
        Bs[kg * 4 + 0][l] = bv.x; Bs[kg * 4 + 1][l] = bv.y;
        Bs[kg * 4 + 2][l] = bv.z; Bs[kg * 4 + 3][l] = bv.w;
        __syncthreads();
#pragma unroll
        for (int kk = 0; kk < 16; ++kk) {
            float a[4], bbx[4];
            *(float4*)&a[0]   = *(const float4*)&As[kk][tm * 4];
            *(float4*)&bbx[0] = *(const float4*)&Bs[kk][tn * 4];
#pragma unroll
            for (int i = 0; i < 4; i++)
#pragma unroll
                for (int j = 0; j < 4; j++)
                    acc[i][j] = fmaf(a[i], bbx[j], acc[i][j]);
        }
        __syncthreads();
    }
#pragma unroll
    for (int i = 0; i < 4; i++)
#pragma unroll
        for (int j = 0; j < 4; j++)
            atomicAdd(&g_att_acc[(tm * 4 + i) * 512 + ot * 64 + tn * 4 + j], acc[i][j]);
}

// =====================================================================
// Kernel 5: grouped rank projection (raw; att & bias applied in k_final)
// =====================================================================
#define RK_ASTR 72
#define RK_BSTR 40
#define RK_APL  (32 * RK_ASTR)
#define RK_BPL  (64 * RK_BSTR)

__global__ __launch_bounds__(256)
void k_rank(const float* __restrict__ in)
{
    __shared__ __align__(16) __half sAh[2][RK_APL], sAl[2][RK_APL];
    __shared__ __align__(16) __half sBh[2][RK_BPL], sBl[2][RK_BPL];

    const int q = blockIdx.x;    // 0..3
    const int s = blockIdx.y;    // 0..7
    const int b = blockIdx.z;    // 0..63
    const int tid = threadIdx.x;
    const int hwb = q * 48;

    const float* img = in + (size_t)(b * 8 + s) * CIN * HWSZ;

    const int acr = tid >> 3;
    const int acg = (tid & 7) * 8;
    const int brr = tid >> 2;
    const int bcg = (tid & 3) * 8;
    const __half* whr = g_rwh + (size_t)(s * 64 + brr) * 256 + bcg;
    const __half* wlr = g_rwl + (size_t)(s * 64 + brr) * 256 + bcg;

    const uint32_t stA_h = smem_u32(&sAh[0][acr * RK_ASTR + acg]);
    const uint32_t stA_l = smem_u32(&sAl[0][acr * RK_ASTR + acg]);
    const uint32_t stB_h = smem_u32(&sBh[0][brr * RK_BSTR + bcg]);
    const uint32_t stB_l = smem_u32(&sBl[0][brr * RK_BSTR + bcg]);
    const uint32_t aplB = RK_APL * 2;
    const uint32_t bplB = RK_BPL * 2;

    const int w    = tid >> 5;
    const int lane = tid & 31;
    const int wm   = w & 3;
    const int wn   = w >> 2;
    const int lr   = lane & 7;
    const int sel  = lane >> 3;

    const uint32_t aOff = (uint32_t)((((sel >> 1) * 8 + lr) * RK_ASTR
                                     + wm * 16 + (sel & 1) * 8)) * 2u;
    const uint32_t bOff = (uint32_t)((wn * 32 + (sel >> 1) * 8 + lr) * RK_BSTR) * 2u
                          + (sel & 1) * 16;

    const uint32_t baseAh = smem_u32(&sAh[0][0]);
    const uint32_t baseAl = smem_u32(&sAl[0][0]);
    const uint32_t baseBh = smem_u32(&sBh[0][0]);
    const uint32_t baseBl = smem_u32(&sBl[0][0]);

    float acc[4][4];
#pragma unroll
    for (int j = 0; j < 4; j++)
#pragma unroll
        for (int c = 0; c < 4; c++) acc[j][c] = 0.f;

    float avv[8];

#define RK_LOAD_A(ST) do {                                                  \
        const float* ar = img + (size_t)((ST) * 32 + acr) * HWSZ + hwb + acg;\
        const int hw0 = hwb + acg;                                          \
        if (hw0 + 7 < HWSZ) {                                               \
            const float4 t0 = *(const float4*)ar;                           \
            const float4 t1 = *(const float4*)(ar + 4);                     \
            avv[0]=t0.x; avv[1]=t0.y; avv[2]=t0.z; avv[3]=t0.w;             \
            avv[4]=t1.x; avv[5]=t1.y; avv[6]=t1.z; avv[7]=t1.w;             \
        } else {                                                            \
            _Pragma("unroll")                                               \
            for (int k2 = 0; k2 < 8; ++k2)                                  \
                avv[k2] = (hw0 + k2 < HWSZ) ? ar[k2] : 0.f;                 \
        }                                                                   \
    } while (0)

#define RK_CPA_B(ST, BUF) do {                                              \
        cpa16(stB_h + (BUF) * bplB, whr + (ST) * 32);                       \
        cpa16(stB_l + (BUF) * bplB, wlr + (ST) * 32);                       \
        CPA_COMMIT();                                                       \
    } while (0)

#define RK_STORE_A(BUF) do {                                                \
        __half h[8], l[8];                                                  \
        _Pragma("unroll")                                                   \
        for (int k2 = 0; k2 < 8; ++k2) split2(avv[k2], h[k2], l[k2]);       \
        asm volatile("st.shared.v4.b32 [%0], {%1,%2,%3,%4};" ::             \
            "r"(stA_h + (BUF) * aplB),                                      \
            "r"(*(const uint32_t*)&h[0]), "r"(*(const uint32_t*)&h[2]),     \
            "r"(*(const uint32_t*)&h[4]), "r"(*(const uint32_t*)&h[6]));    \
        asm volatile("st.shared.v4.b32 [%0], {%1,%2,%3,%4};" ::             \
            "r"(stA_l + (BUF) * aplB),                                      \
            "r"(*(const uint32_t*)&l[0]), "r"(*(const uint32_t*)&l[2]),     \
            "r"(*(const uint32_t*)&l[4]), "r"(*(const uint32_t*)&l[6]));    \
    } while (0)

    RK_CPA_B(0, 0);
    RK_LOAD_A(0);
    RK_STORE_A(0);
    CPA_WAIT0();
    __syncthreads();

    for (int st = 0; st < 8; ++st) {
        const int cur = st & 1;
        if (st + 1 < 8) {
            RK_LOAD_A(st + 1);
            RK_CPA_B(st + 1, cur ^ 1);
        }

#pragma unroll
        for (int ks = 0; ks < 2; ++ks) {
            uint32_t ah[4], al[4];
            const uint32_t ao = cur * aplB + (uint32_t)(ks * 16 * RK_ASTR) * 2u + aOff;
            ldsm4t(ah, baseAh + ao);
            ldsm4t(al, baseAl + ao);
#pragma unroll
            for (int jj = 0; jj < 2; ++jj) {
                uint32_t bh[4], bl2[4];
                const uint32_t bo = cur * bplB + (uint32_t)(jj * 16 * RK_BSTR) * 2u
                                    + ks * 32 + bOff;
                ldsm4(bh, baseBh + bo);
                ldsm4(bl2, baseBl + bo);
#pragma unroll
                for (int t = 0; t < 2; ++t) {
                    const int jn = jj * 2 + t;
                    mma_f16(acc[jn], ah, bh[t * 2], bh[t * 2 + 1]);
                    mma_f16(acc[jn], ah, bl2[t * 2], bl2[t * 2 + 1]);
                    mma_f16(acc[jn], al, bh[t * 2], bh[t * 2 + 1]);
                }
            }
        }

        if (st + 1 < 8) RK_STORE_A(cur ^ 1);
        CPA_WAIT0();
        __syncthreads();
    }

    // ---- epilogue: store RAW gemm to xr[b][r][s][hw]
    const int g  = lane >> 2;
    const int tg = lane & 3;
#pragma unroll
    for (int j = 0; j < 4; j++) {
        const int r0 = wn * 32 + j * 8 + tg * 2;
#pragma unroll
        for (int h = 0; h < 2; h++) {
            const int hw = hwb + wm * 16 + g + h * 8;
            if (hw < HWSZ) {
                g_xr[((size_t)(b * 64 + r0) * 8 + s) * HWSZ + hw]     = acc[j][h * 2 + 0];
                g_xr[((size_t)(b * 64 + r0 + 1) * 8 + s) * HWSZ + hw] = acc[j][h * 2 + 1];
            }
        }
    }
#undef RK_LOAD_A
#undef RK_CPA_B
#undef RK_STORE_A
}

// =====================================================================
// Kernel 6: sigmoid att + argmax + pivot-pool + final linear, fused.
// =====================================================================
__global__ __launch_bounds__(512)
void k_final(const float* __restrict__ b2, const float* __restrict__ rank_b,
             const float* __restrict__ lin_w, const float* __restrict__ lin_b,
             float* __restrict__ out)
{
    __shared__ float pooled[64];
    const int b = blockIdx.x;
    const int tid = threadIdx.x, wid = tid >> 5, lane = tid & 31;

#pragma unroll
    for (int rr = 0; rr < 4; ++rr) {
        const int r = wid * 4 + rr;
        float att[8]; int mi = 0; float best = -1e30f;
#pragma unroll
        for (int s = 0; s < 8; s++) {
            const float v = g_att_acc[b * 512 + s * 64 + r] * (1.f / 144.f)
                            + __ldg(b2 + s * 64 + r);
            const float a = 1.f / (1.f + expf(-v));
            att[s] = a;
            if (a > best) { best = a; mi = s; }
        }
        float rbv[8];
#pragma unroll
        for (int s = 0; s < 8; s++) rbv[s] = __ldg(rank_b + s * 64 + r) * att[s];

        const float* base = g_xr + (size_t)(b * 64 + r) * 8 * HWSZ;
        float sum = 0.f;
        for (int hw = lane; hw < HWSZ; hw += 32) {
            float tot = 0.f, piv = 0.f;
#pragma unroll
            for (int s = 0; s < 8; s++) {
                const float v = base[s * HWSZ + hw] * att[s] + rbv[s];
                tot += v;
                if (s == mi) piv = v;
            }
            sum += piv * (tot - piv);
        }
#pragma unroll
        for (int o = 16; o; o >>= 1) sum += __shfl_down_sync(0xffffffffu, sum, o);
        if (lane == 0) pooled[r] = sum * (1.f / (7.f * 196.f));
    }
    __syncthreads();

    const int o = tid;
    float a = lin_b[o];
#pragma unroll
    for (int r = 0; r < 64; r++)
        a = fmaf(pooled[r], lin_w[o * 64 + r], a);
    out[b * 512 + o] = a;
}

// =====================================================================
extern "C" void kernel_launch(void* const* d_in, const int* in_sizes, int n_in,
                              void* d_out, int out_size)
{
    const float* in = (const float*)d_in[0];
    const float* w1 = (const float*)d_in[1];
    const float* b1 = (const float*)d_in[2];
    const float* w2 = (const float*)d_in[3];
    const float* b2 = (const float*)d_in[4];
    const float* rw = (const float*)d_in[5];
    const float* rb = (const float*)d_in[6];
    const float* lw = (const float*)d_in[7];
    const float* lb = (const float*)d_in[8];
    float* out = (float*)d_out;

    static cudaStream_t s2 = 0;
    static cudaEvent_t evFork = 0, evJoin = 0;
    if (!s2) {
        cudaStreamCreateWithFlags(&s2, cudaStreamNonBlocking);
        cudaEventCreateWithFlags(&evFork, cudaEventDisableTiming);
        cudaEventCreateWithFlags(&evJoin, cudaEventDisableTiming);
    }

    k_init<<<1280, 256>>>(w1, rw);                        // zero + weight split

    // fork after init: k_rank on s2, concurrent with prepA/conv1/gemm2
    cudaEventRecord(evFork, 0);
    cudaStreamWaitEvent(s2, evFork, 0);
    k_rank<<<dim3(4, 8, 64), 256, 0, s2>>>(in);
    cudaEventRecord(evJoin, s2);

    k_prepA<<<dim3(43, 256), 256>>>(in);                  // im2col + split A
    k_conv1<<<dim3(85, 4), 256>>>(b1);
    k_gemm2<<<dim3(8, 32), 256>>>(w2);

    cudaStreamWaitEvent(0, evJoin, 0);
    k_final<<<64, 512>>>(b2, rb, lw, lb, out);
}

// round 15
// speedup vs baseline: 1.0469x; 1.0469x over previous
#include <cuda_runtime.h>
#include <cuda_fp16.h>
#include <math.h>
#include <stdint.h>

// Problem constants
#define BATCH 64
#define SEG   8
#define CIN   256
#define RNK   64
#define HWSZ  196      // 14*14
#define P1    169      // 13*13
#define M1    10816    // BATCH * P1

// ---------------- scratch ----------------
__device__ float  g_awin[BATCH * 2048];            // conv1 window sums
__device__ float  g_att_acc[BATCH * 512];          // conv2-mean accumulator
__device__ float  g_xr[BATCH * RNK * SEG * HWSZ];  // raw rank GEMM [b][r][s][hw]
__device__ __half g_w1h[512 * 1024];               // pre-split conv1 weights (hi)
__device__ __half g_w1l[512 * 1024];               // pre-split conv1 weights (lo)
__device__ __half g_rwh[SEG * RNK * CIN];          // pre-split rank weights (hi)
__device__ __half g_rwl[SEG * RNK * CIN];          // pre-split rank weights (lo)

// ---------------- helpers ----------------
__device__ __forceinline__ uint32_t smem_u32(const void* p) {
    uint32_t a;
    asm("{ .reg .u64 t; cvta.to.shared.u64 t, %1; cvt.u32.u64 %0, t; }"
        : "=r"(a) : "l"(p));
    return a;
}

__device__ __forceinline__ void mma_f16(float* d, const uint32_t* a,
                                        uint32_t b0, uint32_t b1) {
    asm volatile(
        "mma.sync.aligned.m16n8k16.row.col.f32.f16.f16.f32 "
        "{%0,%1,%2,%3},{%4,%5,%6,%7},{%8,%9},{%0,%1,%2,%3};"
        : "+f"(d[0]), "+f"(d[1]), "+f"(d[2]), "+f"(d[3])
        : "r"(a[0]), "r"(a[1]), "r"(a[2]), "r"(a[3]), "r"(b0), "r"(b1));
}

__device__ __forceinline__ void ldsm4(uint32_t* r, uint32_t addr) {
    asm volatile("ldmatrix.sync.aligned.m8n8.x4.shared.b16 {%0,%1,%2,%3}, [%4];"
                 : "=r"(r[0]), "=r"(r[1]), "=r"(r[2]), "=r"(r[3]) : "r"(addr));
}
__device__ __forceinline__ void ldsm4t(uint32_t* r, uint32_t addr) {
    asm volatile("ldmatrix.sync.aligned.m8n8.x4.trans.shared.b16 {%0,%1,%2,%3}, [%4];"
                 : "=r"(r[0]), "=r"(r[1]), "=r"(r[2]), "=r"(r[3]) : "r"(addr));
}

__device__ __forceinline__ void split2(float v, __half& h, __half& l) {
    h = __float2half_rn(v);
    l = __float2half_rn(v - __half2float(h));
}

// cp.async 16B global->shared (used only in k_rank; hidden under conv1)
__device__ __forceinline__ void cpa16(uint32_t dst, const void* src) {
    asm volatile("cp.async.cg.shared.global [%0], [%1], 16;"
                 :: "r"(dst), "l"(__cvta_generic_to_global(src)));
}
#define CPA_COMMIT() asm volatile("cp.async.commit_group;" ::: "memory")
#define CPA_WAIT0()  asm volatile("cp.async.wait_group 0;"  ::: "memory")

// =====================================================================
// Kernel 0: zero buffers + pre-split weights, one kernel.
// =====================================================================
__global__ void k_init(const float* __restrict__ w1,
                       const float* __restrict__ rank_w)
{
    const int blk = blockIdx.x;
    if (blk < 640) {
        const int i = blk * 256 + threadIdx.x;
        if (i < 131072) g_awin[i] = 0.f;
        else            g_att_acc[i - 131072] = 0.f;
    } else if (blk < 1152) {
        const int i = ((blk - 640) * 256 + threadIdx.x) * 4;
        const float4 v = *(const float4*)(w1 + i);
        __half h[4], l[4];
        split2(v.x, h[0], l[0]); split2(v.y, h[1], l[1]);
        split2(v.z, h[2], l[2]); split2(v.w, h[3], l[3]);
        *(uint2*)&g_w1h[i] = *(const uint2*)h;
        *(uint2*)&g_w1l[i] = *(const uint2*)l;
    } else {
        const int i = ((blk - 1152) * 256 + threadIdx.x) * 4;  // 128 blocks cover 131072
        const float4 v = *(const float4*)(rank_w + i);
        __half h[4], l[4];
        split2(v.x, h[0], l[0]); split2(v.y, h[1], l[1]);
        split2(v.z, h[2], l[2]); split2(v.w, h[3], l[3]);
        *(uint2*)&g_rwh[i] = *(const uint2*)h;
        *(uint2*)&g_rwl[i] = *(const uint2*)l;
    }
}

// =====================================================================
// Kernel 1: conv1 + bias + relu + fused window sums, fp16 3-pass mma
//   (proven 188us config: BK=16, 48KB smem, 2 CTA/SM, in-kernel A
//    gather + pre-split B via LDG.128 + STS.128, L1-cached reuse)
// =====================================================================
#define ASTR 24   // halves per row (48B)

__global__ __launch_bounds__(256, 2)
void k_conv1(const float* __restrict__ in, const float* __restrict__ b1)
{
    __shared__ __align__(16) __half sAh[2][128 * ASTR];
    __shared__ __align__(16) __half sAl[2][128 * ASTR];
    __shared__ __align__(16) __half sBh[2][128 * ASTR];
    __shared__ __align__(16) __half sBl[2][128 * ASTR];

    const int tid = threadIdx.x;
    const int mt  = blockIdx.x;   // 0..84
    const int nt  = blockIdx.y;   // 0..3

    const int lm = tid & 127;
    const int lh = tid >> 7;      // k-half: 0 -> k0-7, 1 -> k8-15

    const int m  = mt * 128 + lm;
    const bool mv = (m < M1);
    const int ms = mv ? m : 0;
    const int bb = ms / 169;
    const int p  = ms % 169;
    const int yy = p / 13, xx = p % 13;
    const float* inb = in + (size_t)(bb * 8) * CIN * HWSZ + yy * 14 + xx;
    const __half* w1hp = g_w1h + (size_t)(nt * 128 + lm) * 1024 + lh * 8;
    const __half* w1lp = g_w1l + (size_t)(nt * 128 + lm) * 1024 + lh * 8;

    const uint32_t stAh = smem_u32(&sAh[0][lm * ASTR + lh * 8]);
    const uint32_t stAl = smem_u32(&sAl[0][lm * ASTR + lh * 8]);
    const uint32_t stBh = smem_u32(&sBh[0][lm * ASTR + lh * 8]);
    const uint32_t stBl = smem_u32(&sBl[0][lm * ASTR + lh * 8]);
    const uint32_t bufB = 128 * ASTR * 2;  // bytes per buffer plane

    const int w    = tid >> 5;
    const int lane = tid & 31;
    const int wm   = w & 3;
    const int wn   = w >> 2;
    const int am   = wm * 32;
    const int bn   = wn * 64;

    const int lr  = lane & 7;
    const int sel = lane >> 3;
    const int aRow  = (sel & 1) * 8 + lr;
    const int aByte = (sel >> 1) * 16;
    const int bRow  = (sel >> 1) * 8 + lr;
    const int bByte = (sel & 1) * 16;

    const uint32_t baseAh = smem_u32(&sAh[0][0]);
    const uint32_t baseAl = smem_u32(&sAl[0][0]);
    const uint32_t baseBh = smem_u32(&sBh[0][0]);
    const uint32_t baseBl = smem_u32(&sBl[0][0]);

    float acc[2][8][4];
#pragma unroll
    for (int i = 0; i < 2; i++)
#pragma unroll
        for (int j = 0; j < 8; j++)
#pragma unroll
            for (int c = 0; c < 4; c++) acc[i][j][c] = 0.f;

    float av[8];          // A staging: 2 channels x 4 taps
    uint4 bhv, blv;       // B staging: pre-split halves

#define LOAD_REGS(ST) do {                                                \
        _Pragma("unroll")                                                 \
        for (int cc = 0; cc < 2; ++cc) {                                  \
            const int ch = (ST) * 4 + lh * 2 + cc;                        \
            const float* pA = inb + ((ch >> 5) * CIN + (ch & 31)) * HWSZ; \
            if (mv) { av[cc*4+0] = pA[0];  av[cc*4+1] = pA[1];            \
                      av[cc*4+2] = pA[14]; av[cc*4+3] = pA[15]; }         \
            else    { av[cc*4+0]=av[cc*4+1]=av[cc*4+2]=av[cc*4+3]=0.f; }  \
        }                                                                 \
        bhv = *(const uint4*)(w1hp + (ST) * 16);                          \
        blv = *(const uint4*)(w1lp + (ST) * 16);                          \
    } while (0)

#define STORE_REGS(BUF) do {                                              \
        __half h[8], l[8];                                                \
        _Pragma("unroll")                                                 \
        for (int q = 0; q < 8; ++q) split2(av[q], h[q], l[q]);            \
        asm volatile("st.shared.v4.b32 [%0], {%1,%2,%3,%4};" ::           \
            "r"(stAh + (BUF) * bufB),                                     \
            "r"(*(const uint32_t*)&h[0]), "r"(*(const uint32_t*)&h[2]),   \
            "r"(*(const uint32_t*)&h[4]), "r"(*(const uint32_t*)&h[6]));  \
        asm volatile("st.shared.v4.b32 [%0], {%1,%2,%3,%4};" ::           \
            "r"(stAl + (BUF) * bufB),                                     \
            "r"(*(const uint32_t*)&l[0]), "r"(*(const uint32_t*)&l[2]),   \
            "r"(*(const uint32_t*)&l[4]), "r"(*(const uint32_t*)&l[6]));  \
        asm volatile("st.shared.v4.b32 [%0], {%1,%2,%3,%4};" ::           \
            "r"(stBh + (BUF) * bufB),                                     \
            "r"(bhv.x), "r"(bhv.y), "r"(bhv.z), "r"(bhv.w));              \
        asm volatile("st.shared.v4.b32 [%0], {%1,%2,%3,%4};" ::           \
            "r"(stBl + (BUF) * bufB),                                     \
            "r"(blv.x), "r"(blv.y), "r"(blv.z), "r"(blv.w));              \
    } while (0)

    LOAD_REGS(0);
    STORE_REGS(0);
    __syncthreads();

    for (int st = 0; st < 64; ++st) {
        const int cur = st & 1;
        if (st + 1 < 64) LOAD_REGS(st + 1);

        uint32_t ah[2][4], al[2][4];
#pragma unroll
        for (int i = 0; i < 2; i++) {
            const uint32_t ro = (uint32_t)((am + i * 16 + aRow) * ASTR) * 2u + aByte;
            ldsm4(ah[i], baseAh + cur * bufB + ro);
            ldsm4(al[i], baseAl + cur * bufB + ro);
        }

#pragma unroll
        for (int jj = 0; jj < 4; ++jj) {
            const uint32_t ro = (uint32_t)((bn + jj * 16 + bRow) * ASTR) * 2u + bByte;
            uint32_t bh[4], bl[4];
            ldsm4(bh, baseBh + cur * bufB + ro);
            ldsm4(bl, baseBl + cur * bufB + ro);
#pragma unroll
            for (int t = 0; t < 2; ++t) {
                const int j = jj * 2 + t;
#pragma unroll
                for (int i = 0; i < 2; ++i) {
                    mma_f16(acc[i][j], ah[i], bh[t * 2], bh[t * 2 + 1]);  // hh
                    mma_f16(acc[i][j], ah[i], bl[t * 2], bl[t * 2 + 1]);  // hl
                    mma_f16(acc[i][j], al[i], bh[t * 2], bh[t * 2 + 1]);  // lh
                }
            }
        }

        if (st + 1 < 64) STORE_REGS(cur ^ 1);
        __syncthreads();
    }

    // ---- fused epilogue: bias + relu + window sums -> g_awin atomics
    const int qr = lane >> 2;
    const int qc = lane & 3;
    const int b0 = (mt * 128) / 169;
#pragma unroll
    for (int j = 0; j < 8; j++) {
        const int nbase = nt * 128 + bn + j * 8 + qc * 2;
        const float bia0 = __ldg(b1 + nbase);
        const float bia1 = __ldg(b1 + nbase + 1);
#pragma unroll
        for (int z = 0; z < 2; z++) {
            const float bia = z ? bia1 : bia0;
            float w4[2][4] = {{0.f,0.f,0.f,0.f},{0.f,0.f,0.f,0.f}};
#pragma unroll
            for (int i = 0; i < 2; i++) {
#pragma unroll
                for (int h = 0; h < 2; h++) {
                    const int mr = mt * 128 + am + i * 16 + qr + h * 8;
                    if (mr < M1) {
                        float v = acc[i][j][h * 2 + z] + bia;
                        v = v > 0.f ? v : 0.f;
                        const int bl2 = mr / 169 - b0;
                        const int pp  = mr % 169;
                        const int y   = pp / 13, x = pp - y * 13;
                        if (y < 12) { if (x < 12) w4[bl2][0] += v; if (x > 0) w4[bl2][1] += v; }
                        if (y > 0)  { if (x < 12) w4[bl2][2] += v; if (x > 0) w4[bl2][3] += v; }
                    }
                }
            }
#pragma unroll
            for (int o = 4; o <= 16; o <<= 1)
#pragma unroll
                for (int bl2 = 0; bl2 < 2; bl2++)
#pragma unroll
                    for (int t = 0; t < 4; t++)
                        w4[bl2][t] += __shfl_xor_sync(0xffffffffu, w4[bl2][t], o);
            if (qr == 0) {
                const int n = nbase + z;
#pragma unroll
                for (int bl2 = 0; bl2 < 2; bl2++) {
                    const int bg = b0 + bl2;
#pragma unroll
                    for (int t = 0; t < 4; t++)
                        if (w4[bl2][t] != 0.f)
                            atomicAdd(&g_awin[bg * 2048 + n * 4 + t], w4[bl2][t]);
                }
            }
        }
    }
#undef LOAD_REGS
#undef STORE_REGS
}

// =====================================================================
// Kernel 3: conv2-as-GEMM on window sums. M=64, N=512, K=2048.
//   K split 32 ways (chunk 64) for occupancy.
// =====================================================================
__global__ __launch_bounds__(256)
void k_gemm2(const float* __restrict__ w2)
{
    __shared__ __align__(16) float As[16][64];
    __shared__ __align__(16) float Bs[16][64];

    const int ot = blockIdx.x, ks = blockIdx.y;   // ot 0..7, ks 0..31
    const int tid = threadIdx.x;
    const int l = tid & 63, kg = tid >> 6;
    const int tm = tid >> 4, tn = tid & 15;

    float acc[4][4];
#pragma unroll
    for (int i = 0; i < 4; i++)
#pragma unroll
        for (int j = 0; j < 4; j++) acc[i][j] = 0.f;

    for (int it = 0; it < 4; ++it) {
        const int kb = ks * 64 + it * 16;
        const float4 av = *(const float4*)&g_awin[l * 2048 + kb + kg * 4];
        const float4 bv = *(const float4*)(w2 + (size_t)(ot * 64 + l) * 2048 + kb + kg * 4);
        As[kg * 4 + 0][l] = av.x; As[kg * 4 + 1][l] = av.y;
        As[kg * 4 + 2][l] = av.z; As[kg * 4 + 3][l] = av.w;
        Bs[kg * 4 + 0][l] = bv.x; Bs[kg * 4 + 1][l] = bv.y;
        Bs[kg * 4 + 2][l] = bv.z; Bs[kg * 4 + 3][l] = bv.w;
        __syncthreads();
#pragma unroll
        for (int kk = 0; kk < 16; ++kk) {
            float a[4], bbx[4];
            *(float4*)&a[0]   = *(const float4*)&As[kk][tm * 4];
            *(float4*)&bbx[0] = *(const float4*)&Bs[kk][tn * 4];
#pragma unroll
            for (int i = 0; i < 4; i++)
#pragma unroll
                for (int j = 0; j < 4; j++)
                    acc[i][j] = fmaf(a[i], bbx[j], acc[i][j]);
        }
        __syncthreads();
    }
#pragma unroll
    for (int i = 0; i < 4; i++)
#pragma unroll
        for (int j = 0; j < 4; j++)
            atomicAdd(&g_att_acc[(tm * 4 + i) * 512 + ot * 64 + tn * 4 + j], acc[i][j]);
}

// =====================================================================
// Kernel 5: grouped rank projection (raw; att & bias applied in k_final)
//   Per CTA (q,s,b): C[hw 64][r 64] = x^T . w^T, K=256, fp16 3-pass.
//   4 overlapping hw tiles at bases {0,48,96,144} (provably minimal
//   coverage of 196 with 64-wide tiles; duplicates write identical vals).
// =====================================================================
#define RK_ASTR 72
#define RK_BSTR 40
#define RK_APL  (32 * RK_ASTR)
#define RK_BPL  (64 * RK_BSTR)

__global__ __launch_bounds__(256)
void k_rank(const float* __restrict__ in)
{
    __shared__ __align__(16) __half sAh[2][RK_APL], sAl[2][RK_APL];
    __shared__ __align__(16) __half sBh[2][RK_BPL], sBl[2][RK_BPL];

    const int q = blockIdx.x;    // 0..3
    const int s = blockIdx.y;    // 0..7
    const int b = blockIdx.z;    // 0..63
    const int tid = threadIdx.x;
    const int hwb = q * 48;

    const float* img = in + (size_t)(b * 8 + s) * CIN * HWSZ;

    const int acr = tid >> 3;
    const int acg = (tid & 7) * 8;
    const int brr = tid >> 2;
    const int bcg = (tid & 3) * 8;
    const __half* whr = g_rwh + (size_t)(s * 64 + brr) * 256 + bcg;
    const __half* wlr = g_rwl + (size_t)(s * 64 + brr) * 256 + bcg;

    const uint32_t stA_h = smem_u32(&sAh[0][acr * RK_ASTR + acg]);
    const uint32_t stA_l = smem_u32(&sAl[0][acr * RK_ASTR + acg]);
    const uint32_t stB_h = smem_u32(&sBh[0][brr * RK_BSTR + bcg]);
    const uint32_t stB_l = smem_u32(&sBl[0][brr * RK_BSTR + bcg]);
    const uint32_t aplB = RK_APL * 2;
    const uint32_t bplB = RK_BPL * 2;

    const int w    = tid >> 5;
    const int lane = tid & 31;
    const int wm   = w & 3;
    const int wn   = w >> 2;
    const int lr   = lane & 7;
    const int sel  = lane >> 3;

    const uint32_t aOff = (uint32_t)((((sel >> 1) * 8 + lr) * RK_ASTR
                                     + wm * 16 + (sel & 1) * 8)) * 2u;
    const uint32_t bOff = (uint32_t)((wn * 32 + (sel >> 1) * 8 + lr) * RK_BSTR) * 2u
                          + (sel & 1) * 16;

    const uint32_t baseAh = smem_u32(&sAh[0][0]);
    const uint32_t baseAl = smem_u32(&sAl[0][0]);
    const uint32_t baseBh = smem_u32(&sBh[0][0]);
    const uint32_t baseBl = smem_u32(&sBl[0][0]);

    float acc[4][4];
#pragma unroll
    for (int j = 0; j < 4; j++)
#pragma unroll
        for (int c = 0; c < 4; c++) acc[j][c] = 0.f;

    float avv[8];

#define RK_LOAD_A(ST) do {                                                  \
        const float* ar = img + (size_t)((ST) * 32 + acr) * HWSZ + hwb + acg;\
        const int hw0 = hwb + acg;                                          \
        if (hw0 + 7 < HWSZ) {                                               \
            const float4 t0 = *(const float4*)ar;                           \
            const float4 t1 = *(const float4*)(ar + 4);                     \
            avv[0]=t0.x; avv[1]=t0.y; avv[2]=t0.z; avv[3]=t0.w;             \
            avv[4]=t1.x; avv[5]=t1.y; avv[6]=t1.z; avv[7]=t1.w;             \
        } else {                                                            \
            _Pragma("unroll")                                               \
            for (int k2 = 0; k2 < 8; ++k2)                                  \
                avv[k2] = (hw0 + k2 < HWSZ) ? ar[k2] : 0.f;                 \
        }                                                                   \
    } while (0)

#define RK_CPA_B(ST, BUF) do {                                              \
        cpa16(stB_h + (BUF) * bplB, whr + (ST) * 32);                       \
        cpa16(stB_l + (BUF) * bplB, wlr + (ST) * 32);                       \
        CPA_COMMIT();                                                       \
    } while (0)

#define RK_STORE_A(BUF) do {                                                \
        __half h[8], l[8];                                                  \
        _Pragma("unroll")                                                   \
        for (int k2 = 0; k2 < 8; ++k2) split2(avv[k2], h[k2], l[k2]);       \
        asm volatile("st.shared.v4.b32 [%0], {%1,%2,%3,%4};" ::             \
            "r"(stA_h + (BUF) * aplB),                                      \
            "r"(*(const uint32_t*)&h[0]), "r"(*(const uint32_t*)&h[2]),     \
            "r"(*(const uint32_t*)&h[4]), "r"(*(const uint32_t*)&h[6]));    \
        asm volatile("st.shared.v4.b32 [%0], {%1,%2,%3,%4};" ::             \
            "r"(stA_l + (BUF) * aplB),                                      \
            "r"(*(const uint32_t*)&l[0]), "r"(*(const uint32_t*)&l[2]),     \
            "r"(*(const uint32_t*)&l[4]), "r"(*(const uint32_t*)&l[6]));    \
    } while (0)

    RK_CPA_B(0, 0);
    RK_LOAD_A(0);
    RK_STORE_A(0);
    CPA_WAIT0();
    __syncthreads();

    for (int st = 0; st < 8; ++st) {
        const int cur = st & 1;
        if (st + 1 < 8) {
            RK_LOAD_A(st + 1);
            RK_CPA_B(st + 1, cur ^ 1);
        }

#pragma unroll
        for (int ks = 0; ks < 2; ++ks) {
            uint32_t ah[4], al[4];
            const uint32_t ao = cur * aplB + (uint32_t)(ks * 16 * RK_ASTR) * 2u + aOff;
            ldsm4t(ah, baseAh + ao);
            ldsm4t(al, baseAl + ao);
#pragma unroll
            for (int jj = 0; jj < 2; ++jj) {
                uint32_t bh[4], bl2[4];
                const uint32_t bo = cur * bplB + (uint32_t)(jj * 16 * RK_BSTR) * 2u
                                    + ks * 32 + bOff;
                ldsm4(bh, baseBh + bo);
                ldsm4(bl2, baseBl + bo);
#pragma unroll
                for (int t = 0; t < 2; ++t) {
                    const int jn = jj * 2 + t;
                    mma_f16(acc[jn], ah, bh[t * 2], bh[t * 2 + 1]);
                    mma_f16(acc[jn], ah, bl2[t * 2], bl2[t * 2 + 1]);
                    mma_f16(acc[jn], al, bh[t * 2], bh[t * 2 + 1]);
                }
            }
        }

        if (st + 1 < 8) RK_STORE_A(cur ^ 1);
        CPA_WAIT0();
        __syncthreads();
    }

    // ---- epilogue: store RAW gemm to xr[b][r][s][hw]
    const int g  = lane >> 2;
    const int tg = lane & 3;
#pragma unroll
    for (int j = 0; j < 4; j++) {
        const int r0 = wn * 32 + j * 8 + tg * 2;
#pragma unroll
        for (int h = 0; h < 2; h++) {
            const int hw = hwb + wm * 16 + g + h * 8;
            if (hw < HWSZ) {
                g_xr[((size_t)(b * 64 + r0) * 8 + s) * HWSZ + hw]     = acc[j][h * 2 + 0];
                g_xr[((size_t)(b * 64 + r0 + 1) * 8 + s) * HWSZ + hw] = acc[j][h * 2 + 1];
            }
        }
    }
#undef RK_LOAD_A
#undef RK_CPA_B
#undef RK_STORE_A
}

// =====================================================================
// Kernel 6: sigmoid att + argmax + pivot-pool + final linear, fused.
// =====================================================================
__global__ __launch_bounds__(512)
void k_final(const float* __restrict__ b2, const float* __restrict__ rank_b,
             const float* __restrict__ lin_w, const float* __restrict__ lin_b,
             float* __restrict__ out)
{
    __shared__ float pooled[64];
    const int b = blockIdx.x;
    const int tid = threadIdx.x, wid = tid >> 5, lane = tid & 31;

#pragma unroll
    for (int rr = 0; rr < 4; ++rr) {
        const int r = wid * 4 + rr;
        float att[8]; int mi = 0; float best = -1e30f;
#pragma unroll
        for (int s = 0; s < 8; s++) {
            const float v = g_att_acc[b * 512 + s * 64 + r] * (1.f / 144.f)
                            + __ldg(b2 + s * 64 + r);
            const float a = 1.f / (1.f + expf(-v));
            att[s] = a;
            if (a > best) { best = a; mi = s; }
        }
        float rbv[8];
#pragma unroll
        for (int s = 0; s < 8; s++) rbv[s] = __ldg(rank_b + s * 64 + r) * att[s];

        const float* base = g_xr + (size_t)(b * 64 + r) * 8 * HWSZ;
        float sum = 0.f;
        for (int hw = lane; hw < HWSZ; hw += 32) {
            float tot = 0.f, piv = 0.f;
#pragma unroll
            for (int s = 0; s < 8; s++) {
                const float v = base[s * HWSZ + hw] * att[s] + rbv[s];
                tot += v;
                if (s == mi) piv = v;
            }
            sum += piv * (tot - piv);
        }
#pragma unroll
        for (int o = 16; o; o >>= 1) sum += __shfl_down_sync(0xffffffffu, sum, o);
        if (lane == 0) pooled[r] = sum * (1.f / (7.f * 196.f));
    }
    __syncthreads();

    const int o = tid;
    float a = lin_b[o];
#pragma unroll
    for (int r = 0; r < 64; r++)
        a = fmaf(pooled[r], lin_w[o * 64 + r], a);
    out[b * 512 + o] = a;
}

// =====================================================================
extern "C" void kernel_launch(void* const* d_in, const int* in_sizes, int n_in,
                              void* d_out, int out_size)
{
    const float* in = (const float*)d_in[0];
    const float* w1 = (const float*)d_in[1];
    const float* b1 = (const float*)d_in[2];
    const float* w2 = (const float*)d_in[3];
    const float* b2 = (const float*)d_in[4];
    const float* rw = (const float*)d_in[5];
    const float* rb = (const float*)d_in[6];
    const float* lw = (const float*)d_in[7];
    const float* lb = (const float*)d_in[8];
    float* out = (float*)d_out;

    static cudaStream_t s2 = 0;
    static cudaEvent_t evFork = 0, evJoin = 0;
    if (!s2) {
        cudaStreamCreateWithFlags(&s2, cudaStreamNonBlocking);
        cudaEventCreateWithFlags(&evFork, cudaEventDisableTiming);
        cudaEventCreateWithFlags(&evJoin, cudaEventDisableTiming);
    }

    k_init<<<1280, 256>>>(w1, rw);                        // zero + weight split

    // fork after init: k_rank on s2, concurrent with conv1/gemm2
    cudaEventRecord(evFork, 0);
    cudaStreamWaitEvent(s2, evFork, 0);
    k_rank<<<dim3(4, 8, 64), 256, 0, s2>>>(in);           // 4 tiles (minimal cover)
    cudaEventRecord(evJoin, s2);

    k_conv1<<<dim3(85, 4), 256>>>(in, b1);
    k_gemm2<<<dim3(8, 32), 256>>>(w2);

    cudaStreamWaitEvent(0, evJoin, 0);
    k_final<<<64, 512>>>(b2, rb, lw, lb, out);
}

// round 16
// speedup vs baseline: 1.1228x; 1.0725x over previous
#include <cuda_runtime.h>
#include <cuda_fp16.h>
#include <math.h>
#include <stdint.h>

// Problem constants
#define BATCH 64
#define SEG   8
#define CIN   256
#define RNK   64
#define HWSZ  196      // 14*14
#define P1    169      // 13*13
#define M1    10816    // BATCH * P1

// ---------------- scratch ----------------
__device__ float  g_awin[BATCH * 2048];            // conv1 window sums
__device__ float  g_att_acc[BATCH * 512];          // conv2-mean accumulator
__device__ float  g_xr[BATCH * RNK * SEG * HWSZ];  // raw rank GEMM [b][r][s][hw]
__device__ __half g_w1h[512 * 1024];               // pre-split conv1 weights (hi)
__device__ __half g_w1l[512 * 1024];               // pre-split conv1 weights (lo)
__device__ __half g_rwh[SEG * RNK * CIN];          // pre-split rank weights (hi)
__device__ __half g_rwl[SEG * RNK * CIN];          // pre-split rank weights (lo)

// ---------------- helpers ----------------
__device__ __forceinline__ uint32_t smem_u32(const void* p) {
    uint32_t a;
    asm("{ .reg .u64 t; cvta.to.shared.u64 t, %1; cvt.u32.u64 %0, t; }"
        : "=r"(a) : "l"(p));
    return a;
}

__device__ __forceinline__ void mma_f16(float* d, const uint32_t* a,
                                        uint32_t b0, uint32_t b1) {
    asm volatile(
        "mma.sync.aligned.m16n8k16.row.col.f32.f16.f16.f32 "
        "{%0,%1,%2,%3},{%4,%5,%6,%7},{%8,%9},{%0,%1,%2,%3};"
        : "+f"(d[0]), "+f"(d[1]), "+f"(d[2]), "+f"(d[3])
        : "r"(a[0]), "r"(a[1]), "r"(a[2]), "r"(a[3]), "r"(b0), "r"(b1));
}

__device__ __forceinline__ void ldsm4(uint32_t* r, uint32_t addr) {
    asm volatile("ldmatrix.sync.aligned.m8n8.x4.shared.b16 {%0,%1,%2,%3}, [%4];"
                 : "=r"(r[0]), "=r"(r[1]), "=r"(r[2]), "=r"(r[3]) : "r"(addr));
}
__device__ __forceinline__ void ldsm4t(uint32_t* r, uint32_t addr) {
    asm volatile("ldmatrix.sync.aligned.m8n8.x4.trans.shared.b16 {%0,%1,%2,%3}, [%4];"
                 : "=r"(r[0]), "=r"(r[1]), "=r"(r[2]), "=r"(r[3]) : "r"(addr));
}

__device__ __forceinline__ void split2(float v, __half& h, __half& l) {
    h = __float2half_rn(v);
    l = __float2half_rn(v - __half2float(h));
}

__device__ __forceinline__ void cpa16(uint32_t dst, const void* src) {
    asm volatile("cp.async.cg.shared.global [%0], [%1], 16;"
                 :: "r"(dst), "l"(__cvta_generic_to_global(src)));
}
#define CPA_COMMIT() asm volatile("cp.async.commit_group;" ::: "memory")
#define CPA_WAIT0()  asm volatile("cp.async.wait_group 0;"  ::: "memory")

// =====================================================================
// Kernel 0: zero buffers + pre-split weights, one kernel.
// =====================================================================
__global__ void k_init(const float* __restrict__ w1,
                       const float* __restrict__ rank_w)
{
    const int blk = blockIdx.x;
    if (blk < 640) {
        const int i = blk * 256 + threadIdx.x;
        if (i < 131072) g_awin[i] = 0.f;
        else            g_att_acc[i - 131072] = 0.f;
    } else if (blk < 1152) {
        const int i = ((blk - 640) * 256 + threadIdx.x) * 4;
        const float4 v = *(const float4*)(w1 + i);
        __half h[4], l[4];
        split2(v.x, h[0], l[0]); split2(v.y, h[1], l[1]);
        split2(v.z, h[2], l[2]); split2(v.w, h[3], l[3]);
        *(uint2*)&g_w1h[i] = *(const uint2*)h;
        *(uint2*)&g_w1l[i] = *(const uint2*)l;
    } else {
        const int i = ((blk - 1152) * 256 + threadIdx.x) * 4;  // 128 blocks cover 131072
        const float4 v = *(const float4*)(rank_w + i);
        __half h[4], l[4];
        split2(v.x, h[0], l[0]); split2(v.y, h[1], l[1]);
        split2(v.z, h[2], l[2]); split2(v.w, h[3], l[3]);
        *(uint2*)&g_rwh[i] = *(const uint2*)h;
        *(uint2*)&g_rwl[i] = *(const uint2*)l;
    }
}

// =====================================================================
// Fused main kernel: bids [0,340) = conv1 body, [340,2388) = rank body.
//   Both use 256 threads; 48KB dynamic smem overlay.
// =====================================================================
#define ASTR 24                          // conv: halves per row (48B)
#define CV_PLB  (128 * ASTR * 2)         // conv: bytes per plane (6144)
#define RK_ASTR 72
#define RK_BSTR 40
#define RK_APLB (32 * RK_ASTR * 2)       // rank A plane bytes (4608)
#define RK_BPLB (64 * RK_BSTR * 2)       // rank B plane bytes (5120)
#define SMEM_MAIN 49152

__global__ __launch_bounds__(256, 2)
void k_main(const float* __restrict__ in, const float* __restrict__ b1)
{
    extern __shared__ __align__(16) char dyn[];
    const uint32_t dynB = smem_u32(dyn);
    const int tid = threadIdx.x;

    if (blockIdx.x < 340) {
        // ============================ conv1 body ============================
        const int mt = blockIdx.x % 85;
        const int nt = blockIdx.x / 85;

        const int lm = tid & 127;
        const int lh = tid >> 7;

        const int m  = mt * 128 + lm;
        const bool mv = (m < M1);
        const int ms = mv ? m : 0;
        const int bb = ms / 169;
        const int p  = ms % 169;
        const int yy = p / 13, xx = p % 13;
        const float* inb = in + (size_t)(bb * 8) * CIN * HWSZ + yy * 14 + xx;
        const __half* w1hp = g_w1h + (size_t)(nt * 128 + lm) * 1024 + lh * 8;
        const __half* w1lp = g_w1l + (size_t)(nt * 128 + lm) * 1024 + lh * 8;

        // smem overlay: Ah[2] | Al[2] | Bh[2] | Bl[2], plane = CV_PLB
        const uint32_t baseAh = dynB;
        const uint32_t baseAl = dynB + 2 * CV_PLB;
        const uint32_t baseBh = dynB + 4 * CV_PLB;
        const uint32_t baseBl = dynB + 6 * CV_PLB;
        const uint32_t rowOff = (uint32_t)(lm * ASTR + lh * 8) * 2u;
        const uint32_t stAh = baseAh + rowOff;
        const uint32_t stAl = baseAl + rowOff;
        const uint32_t stBh = baseBh + rowOff;
        const uint32_t stBl = baseBl + rowOff;

        const int w    = tid >> 5;
        const int lane = tid & 31;
        const int wm   = w & 3;
        const int wn   = w >> 2;
        const int am   = wm * 32;
        const int bn   = wn * 64;

        const int lr  = lane & 7;
        const int sel = lane >> 3;
        const int aRow  = (sel & 1) * 8 + lr;
        const int aByte = (sel >> 1) * 16;
        const int bRow  = (sel >> 1) * 8 + lr;
        const int bByte = (sel & 1) * 16;

        float acc[2][8][4];
#pragma unroll
        for (int i = 0; i < 2; i++)
#pragma unroll
            for (int j = 0; j < 8; j++)
#pragma unroll
                for (int c = 0; c < 4; c++) acc[i][j][c] = 0.f;

        float av[8];
        uint4 bhv, blv;

#define LOAD_REGS(ST) do {                                                \
        _Pragma("unroll")                                                 \
        for (int cc = 0; cc < 2; ++cc) {                                  \
            const int ch = (ST) * 4 + lh * 2 + cc;                        \
            const float* pA = inb + ((ch >> 5) * CIN + (ch & 31)) * HWSZ; \
            if (mv) { av[cc*4+0] = pA[0];  av[cc*4+1] = pA[1];            \
                      av[cc*4+2] = pA[14]; av[cc*4+3] = pA[15]; }         \
            else    { av[cc*4+0]=av[cc*4+1]=av[cc*4+2]=av[cc*4+3]=0.f; }  \
        }                                                                 \
        bhv = *(const uint4*)(w1hp + (ST) * 16);                          \
        blv = *(const uint4*)(w1lp + (ST) * 16);                          \
    } while (0)

#define STORE_REGS(BUF) do {                                              \
        __half h[8], l[8];                                                \
        _Pragma("unroll")                                                 \
        for (int q = 0; q < 8; ++q) split2(av[q], h[q], l[q]);            \
        asm volatile("st.shared.v4.b32 [%0], {%1,%2,%3,%4};" ::           \
            "r"(stAh + (BUF) * CV_PLB),                                   \
            "r"(*(const uint32_t*)&h[0]), "r"(*(const uint32_t*)&h[2]),   \
            "r"(*(const uint32_t*)&h[4]), "r"(*(const uint32_t*)&h[6]));  \
        asm volatile("st.shared.v4.b32 [%0], {%1,%2,%3,%4};" ::           \
            "r"(stAl + (BUF) * CV_PLB),                                   \
            "r"(*(const uint32_t*)&l[0]), "r"(*(const uint32_t*)&l[2]),   \
            "r"(*(const uint32_t*)&l[4]), "r"(*(const uint32_t*)&l[6]));  \
        asm volatile("st.shared.v4.b32 [%0], {%1,%2,%3,%4};" ::           \
            "r"(stBh + (BUF) * CV_PLB),                                   \
            "r"(bhv.x), "r"(bhv.y), "r"(bhv.z), "r"(bhv.w));              \
        asm volatile("st.shared.v4.b32 [%0], {%1,%2,%3,%4};" ::           \
            "r"(stBl + (BUF) * CV_PLB),                                   \
            "r"(blv.x), "r"(blv.y), "r"(blv.z), "r"(blv.w));              \
    } while (0)

        LOAD_REGS(0);
        STORE_REGS(0);
        __syncthreads();

        for (int st = 0; st < 64; ++st) {
            const int cur = st & 1;
            if (st + 1 < 64) LOAD_REGS(st + 1);

            uint32_t ah[2][4], al[2][4];
#pragma unroll
            for (int i = 0; i < 2; i++) {
                const uint32_t ro = (uint32_t)((am + i * 16 + aRow) * ASTR) * 2u + aByte;
                ldsm4(ah[i], baseAh + cur * CV_PLB + ro);
                ldsm4(al[i], baseAl + cur * CV_PLB + ro);
            }

#pragma unroll
            for (int jj = 0; jj < 4; ++jj) {
                const uint32_t ro = (uint32_t)((bn + jj * 16 + bRow) * ASTR) * 2u + bByte;
                uint32_t bh[4], bl[4];
                ldsm4(bh, baseBh + cur * CV_PLB + ro);
                ldsm4(bl, baseBl + cur * CV_PLB + ro);
#pragma unroll
                for (int t = 0; t < 2; ++t) {
                    const int j = jj * 2 + t;
#pragma unroll
                    for (int i = 0; i < 2; ++i) {
                        mma_f16(acc[i][j], ah[i], bh[t * 2], bh[t * 2 + 1]);  // hh
                        mma_f16(acc[i][j], ah[i], bl[t * 2], bl[t * 2 + 1]);  // hl
                        mma_f16(acc[i][j], al[i], bh[t * 2], bh[t * 2 + 1]);  // lh
                    }
                }
            }

            if (st + 1 < 64) STORE_REGS(cur ^ 1);
            __syncthreads();
        }

        // ---- fused epilogue: bias + relu + window sums -> g_awin atomics
        const int qr = lane >> 2;
        const int qc = lane & 3;
        const int b0 = (mt * 128) / 169;
#pragma unroll
        for (int j = 0; j < 8; j++) {
            const int nbase = nt * 128 + bn + j * 8 + qc * 2;
            const float bia0 = __ldg(b1 + nbase);
            const float bia1 = __ldg(b1 + nbase + 1);
#pragma unroll
            for (int z = 0; z < 2; z++) {
                const float bia = z ? bia1 : bia0;
                float w4[2][4] = {{0.f,0.f,0.f,0.f},{0.f,0.f,0.f,0.f}};
#pragma unroll
                for (int i = 0; i < 2; i++) {
#pragma unroll
                    for (int h = 0; h < 2; h++) {
                        const int mr = mt * 128 + am + i * 16 + qr + h * 8;
                        if (mr < M1) {
                            float v = acc[i][j][h * 2 + z] + bia;
                            v = v > 0.f ? v : 0.f;
                            const int bl2 = mr / 169 - b0;
                            const int pp  = mr % 169;
                            const int y   = pp / 13, x = pp - y * 13;
                            if (y < 12) { if (x < 12) w4[bl2][0] += v; if (x > 0) w4[bl2][1] += v; }
                            if (y > 0)  { if (x < 12) w4[bl2][2] += v; if (x > 0) w4[bl2][3] += v; }
                        }
                    }
                }
#pragma unroll
                for (int o = 4; o <= 16; o <<= 1)
#pragma unroll
                    for (int bl2 = 0; bl2 < 2; bl2++)
#pragma unroll
                        for (int t = 0; t < 4; t++)
                            w4[bl2][t] += __shfl_xor_sync(0xffffffffu, w4[bl2][t], o);
                if (qr == 0) {
                    const int n = nbase + z;
#pragma unroll
                    for (int bl2 = 0; bl2 < 2; bl2++) {
                        const int bg = b0 + bl2;
#pragma unroll
                        for (int t = 0; t < 4; t++)
                            if (w4[bl2][t] != 0.f)
                                atomicAdd(&g_awin[bg * 2048 + n * 4 + t], w4[bl2][t]);
                    }
                }
            }
        }
#undef LOAD_REGS
#undef STORE_REGS
    } else {
        // ============================ rank body ============================
        const int rid = blockIdx.x - 340;
        const int q = rid & 3;           // 0..3
        const int s = (rid >> 2) & 7;    // 0..7
        const int b = rid >> 5;          // 0..63
        const int hwb = q * 48;

        const float* img = in + (size_t)(b * 8 + s) * CIN * HWSZ;

        const int acr = tid >> 3;
        const int acg = (tid & 7) * 8;
        const int brr = tid >> 2;
        const int bcg = (tid & 3) * 8;
        const __half* whr = g_rwh + (size_t)(s * 64 + brr) * 256 + bcg;
        const __half* wlr = g_rwl + (size_t)(s * 64 + brr) * 256 + bcg;

        // smem overlay: Ah[2] | Al[2] | Bh[2] | Bl[2]
        const uint32_t baseAh = dynB;
        const uint32_t baseAl = dynB + 2 * RK_APLB;
        const uint32_t baseBh = dynB + 4 * RK_APLB;
        const uint32_t baseBl = dynB + 4 * RK_APLB + 2 * RK_BPLB;
        const uint32_t stA_h = baseAh + (uint32_t)(acr * RK_ASTR + acg) * 2u;
        const uint32_t stA_l = baseAl + (uint32_t)(acr * RK_ASTR + acg) * 2u;
        const uint32_t stB_h = baseBh + (uint32_t)(brr * RK_BSTR + bcg) * 2u;
        const uint32_t stB_l = baseBl + (uint32_t)(brr * RK_BSTR + bcg) * 2u;

        const int w    = tid >> 5;
        const int lane = tid & 31;
        const int wm   = w & 3;
        const int wn   = w >> 2;
        const int lr   = lane & 7;
        const int sel  = lane >> 3;

        const uint32_t aOff = (uint32_t)((((sel >> 1) * 8 + lr) * RK_ASTR
                                         + wm * 16 + (sel & 1) * 8)) * 2u;
        const uint32_t bOff = (uint32_t)((wn * 32 + (sel >> 1) * 8 + lr) * RK_BSTR) * 2u
                              + (sel & 1) * 16;

        float acc[4][4];
#pragma unroll
        for (int j = 0; j < 4; j++)
#pragma unroll
            for (int c = 0; c < 4; c++) acc[j][c] = 0.f;

        float avv[8];

#define RK_LOAD_A(ST) do {                                                  \
        const float* ar = img + (size_t)((ST) * 32 + acr) * HWSZ + hwb + acg;\
        const int hw0 = hwb + acg;                                          \
        if (hw0 + 7 < HWSZ) {                                               \
            const float4 t0 = *(const float4*)ar;                           \
            const float4 t1 = *(const float4*)(ar + 4);                     \
            avv[0]=t0.x; avv[1]=t0.y; avv[2]=t0.z; avv[3]=t0.w;             \
            avv[4]=t1.x; avv[5]=t1.y; avv[6]=t1.z; avv[7]=t1.w;             \
        } else {                                                            \
            _Pragma("unroll")                                               \
            for (int k2 = 0; k2 < 8; ++k2)                                  \
                avv[k2] = (hw0 + k2 < HWSZ) ? ar[k2] : 0.f;                 \
        }                                                                   \
    } while (0)

#define RK_CPA_B(ST, BUF) do {                                              \
        cpa16(stB_h + (BUF) * RK_BPLB, whr + (ST) * 32);                    \
        cpa16(stB_l + (BUF) * RK_BPLB, wlr + (ST) * 32);                    \
        CPA_COMMIT();                                                       \
    } while (0)

#define RK_STORE_A(BUF) do {                                                \
        __half h[8], l[8];                                                  \
        _Pragma("unroll")                                                   \
        for (int k2 = 0; k2 < 8; ++k2) split2(avv[k2], h[k2], l[k2]);       \
        asm volatile("st.shared.v4.b32 [%0], {%1,%2,%3,%4};" ::             \
            "r"(stA_h + (BUF) * RK_APLB),                                   \
            "r"(*(const uint32_t*)&h[0]), "r"(*(const uint32_t*)&h[2]),     \
            "r"(*(const uint32_t*)&h[4]), "r"(*(const uint32_t*)&h[6]));    \
        asm volatile("st.shared.v4.b32 [%0], {%1,%2,%3,%4};" ::             \
            "r"(stA_l + (BUF) * RK_APLB),                                   \
            "r"(*(const uint32_t*)&l[0]), "r"(*(const uint32_t*)&l[2]),     \
            "r"(*(const uint32_t*)&l[4]), "r"(*(const uint32_t*)&l[6]));    \
    } while (0)

        RK_CPA_B(0, 0);
        RK_LOAD_A(0);
        RK_STORE_A(0);
        CPA_WAIT0();
        __syncthreads();

        for (int st = 0; st < 8; ++st) {
            const int cur = st & 1;
            if (st + 1 < 8) {
                RK_LOAD_A(st + 1);
                RK_CPA_B(st + 1, cur ^ 1);
            }

#pragma unroll
            for (int ks = 0; ks < 2; ++ks) {
                uint32_t ah[4], al[4];
                const uint32_t ao = cur * RK_APLB + (uint32_t)(ks * 16 * RK_ASTR) * 2u + aOff;
                ldsm4t(ah, baseAh + ao);
                ldsm4t(al, baseAl + ao - 0 + 2 * RK_APLB - 2 * RK_APLB);  // == baseAl + ao
#pragma unroll
                for (int jj = 0; jj < 2; ++jj) {
                    uint32_t bh[4], bl2[4];
                    const uint32_t bo = cur * RK_BPLB + (uint32_t)(jj * 16 * RK_BSTR) * 2u
                                        + ks * 32 + bOff;
                    ldsm4(bh, baseBh + bo);
                    ldsm4(bl2, baseBl + bo);
#pragma unroll
                    for (int t = 0; t < 2; ++t) {
                        const int jn = jj * 2 + t;
                        mma_f16(acc[jn], ah, bh[t * 2], bh[t * 2 + 1]);
                        mma_f16(acc[jn], ah, bl2[t * 2], bl2[t * 2 + 1]);
                        mma_f16(acc[jn], al, bh[t * 2], bh[t * 2 + 1]);
                    }
                }
            }

            if (st + 1 < 8) RK_STORE_A(cur ^ 1);
            CPA_WAIT0();
            __syncthreads();
        }

        // ---- epilogue: store RAW gemm to xr[b][r][s][hw]
        const int g  = lane >> 2;
        const int tg = lane & 3;
#pragma unroll
        for (int j = 0; j < 4; j++) {
            const int r0 = wn * 32 + j * 8 + tg * 2;
#pragma unroll
            for (int h = 0; h < 2; h++) {
                const int hw = hwb + wm * 16 + g + h * 8;
                if (hw < HWSZ) {
                    g_xr[((size_t)(b * 64 + r0) * 8 + s) * HWSZ + hw]     = acc[j][h * 2 + 0];
                    g_xr[((size_t)(b * 64 + r0 + 1) * 8 + s) * HWSZ + hw] = acc[j][h * 2 + 1];
                }
            }
        }
#undef RK_LOAD_A
#undef RK_CPA_B
#undef RK_STORE_A
    }
}

// =====================================================================
// Kernel 3: conv2-as-GEMM on window sums. M=64, N=512, K=2048.
// =====================================================================
__global__ __launch_bounds__(256)
void k_gemm2(const float* __restrict__ w2)
{
    __shared__ __align__(16) float As[16][64];
    __shared__ __align__(16) float Bs[16][64];

    const int ot = blockIdx.x, ks = blockIdx.y;   // ot 0..7, ks 0..31
    const int tid = threadIdx.x;
    const int l = tid & 63, kg = tid >> 6;
    const int tm = tid >> 4, tn = tid & 15;

    float acc[4][4];
#pragma unroll
    for (int i = 0; i < 4; i++)
#pragma unroll
        for (int j = 0; j < 4; j++) acc[i][j] = 0.f;

    for (int it = 0; it < 4; ++it) {
        const int kb = ks * 64 + it * 16;
        const float4 av = *(const float4*)&g_awin[l * 2048 + kb + kg * 4];
        const float4 bv = *(const float4*)(w2 + (size_t)(ot * 64 + l) * 2048 + kb + kg * 4);
        As[kg * 4 + 0][l] = av.x; As[kg * 4 + 1][l] = av.y;
        As[kg * 4 + 2][l] = av.z; As[kg * 4 + 3][l] = av.w;
        Bs[kg * 4 + 0][l] = bv.x; Bs[kg * 4 + 1][l] = bv.y;
        Bs[kg * 4 + 2][l] = bv.z; Bs[kg * 4 + 3][l] = bv.w;
        __syncthreads();
#pragma unroll
        for (int kk = 0; kk < 16; ++kk) {
            float a[4], bbx[4];
            *(float4*)&a[0]   = *(const float4*)&As[kk][tm * 4];
            *(float4*)&bbx[0] = *(const float4*)&Bs[kk][tn * 4];
#pragma unroll
            for (int i = 0; i < 4; i++)
#pragma unroll
                for (int j = 0; j < 4; j++)
                    acc[i][j] = fmaf(a[i], bbx[j], acc[i][j]);
        }
        __syncthreads();
    }
#pragma unroll
    for (int i = 0; i < 4; i++)
#pragma unroll
        for (int j = 0; j < 4; j++)
            atomicAdd(&g_att_acc[(tm * 4 + i) * 512 + ot * 64 + tn * 4 + j], acc[i][j]);
}

// =====================================================================
// Kernel 6: sigmoid att + argmax + pivot-pool + final linear, fused.
// =====================================================================
__global__ __launch_bounds__(512)
void k_final(const float* __restrict__ b2, const float* __restrict__ rank_b,
             const float* __restrict__ lin_w, const float* __restrict__ lin_b,
             float* __restrict__ out)
{
    __shared__ float pooled[64];
    const int b = blockIdx.x;
    const int tid = threadIdx.x, wid = tid >> 5, lane = tid & 31;

#pragma unroll
    for (int rr = 0; rr < 4; ++rr) {
        const int r = wid * 4 + rr;
        float att[8]; int mi = 0; float best = -1e30f;
#pragma unroll
        for (int s = 0; s < 8; s++) {
            const float v = g_att_acc[b * 512 + s * 64 + r] * (1.f / 144.f)
                            + __ldg(b2 + s * 64 + r);
            const float a = 1.f / (1.f + expf(-v));
            att[s] = a;
            if (a > best) { best = a; mi = s; }
        }
        float rbv[8];
#pragma unroll
        for (int s = 0; s < 8; s++) rbv[s] = __ldg(rank_b + s * 64 + r) * att[s];

        const float* base = g_xr + (size_t)(b * 64 + r) * 8 * HWSZ;
        float sum = 0.f;
        for (int hw = lane; hw < HWSZ; hw += 32) {
            float tot = 0.f, piv = 0.f;
#pragma unroll
            for (int s = 0; s < 8; s++) {
                const float v = base[s * HWSZ + hw] * att[s] + rbv[s];
                tot += v;
                if (s == mi) piv = v;
            }
            sum += piv * (tot - piv);
        }
#pragma unroll
        for (int o = 16; o; o >>= 1) sum += __shfl_down_sync(0xffffffffu, sum, o);
        if (lane == 0) pooled[r] = sum * (1.f / (7.f * 196.f));
    }
    __syncthreads();

    const int o = tid;
    float a = lin_b[o];
#pragma unroll
    for (int r = 0; r < 64; r++)
        a = fmaf(pooled[r], lin_w[o * 64 + r], a);
    out[b * 512 + o] = a;
}

// =====================================================================
extern "C" void kernel_launch(void* const* d_in, const int* in_sizes, int n_in,
                              void* d_out, int out_size)
{
    const float* in = (const float*)d_in[0];
    const float* w1 = (const float*)d_in[1];
    const float* b1 = (const float*)d_in[2];
    const float* w2 = (const float*)d_in[3];
    const float* b2 = (const float*)d_in[4];
    const float* rw = (const float*)d_in[5];
    const float* rb = (const float*)d_in[6];
    const float* lw = (const float*)d_in[7];
    const float* lb = (const float*)d_in[8];
    float* out = (float*)d_out;

    k_init <<<1280, 256>>>(w1, rw);                 // zero + weight split
    k_main <<<2388, 256, SMEM_MAIN>>>(in, b1);      // conv1 + rank fused grid
    k_gemm2<<<dim3(8, 32), 256>>>(w2);
    k_final<<<64, 512>>>(b2, rb, lw, lb, out);
}

// round 17
// speedup vs baseline: 1.2512x; 1.1144x over previous
#include <cuda_runtime.h>
#include <cuda_fp16.h>
#include <math.h>
#include <stdint.h>

// Problem constants
#define BATCH 64
#define SEG   8
#define CIN   256
#define RNK   64
#define HWSZ  196      // 14*14
#define P1    169      // 13*13
#define M1    10816    // BATCH * P1

// ---------------- scratch ----------------
__device__ float  g_awin[BATCH * 2048];            // conv1 window sums
__device__ float  g_att_acc[BATCH * 512];          // conv2-mean accumulator
__device__ float  g_xr[BATCH * RNK * SEG * HWSZ];  // raw rank GEMM [b][r][s][hw]
__device__ float  g_pool[BATCH * RNK];             // pooled y [b][r]
__device__ __half g_w1h[512 * 1024];               // pre-split conv1 weights (hi)
__device__ __half g_w1l[512 * 1024];               // pre-split conv1 weights (lo)
__device__ __half g_rwh[SEG * RNK * CIN];          // pre-split rank weights (hi)
__device__ __half g_rwl[SEG * RNK * CIN];          // pre-split rank weights (lo)

// ---------------- helpers ----------------
__device__ __forceinline__ uint32_t smem_u32(const void* p) {
    uint32_t a;
    asm("{ .reg .u64 t; cvta.to.shared.u64 t, %1; cvt.u32.u64 %0, t; }"
        : "=r"(a) : "l"(p));
    return a;
}

__device__ __forceinline__ void mma_f16(float* d, const uint32_t* a,
                                        uint32_t b0, uint32_t b1) {
    asm volatile(
        "mma.sync.aligned.m16n8k16.row.col.f32.f16.f16.f32 "
        "{%0,%1,%2,%3},{%4,%5,%6,%7},{%8,%9},{%0,%1,%2,%3};"
        : "+f"(d[0]), "+f"(d[1]), "+f"(d[2]), "+f"(d[3])
        : "r"(a[0]), "r"(a[1]), "r"(a[2]), "r"(a[3]), "r"(b0), "r"(b1));
}

__device__ __forceinline__ void ldsm4(uint32_t* r, uint32_t addr) {
    asm volatile("ldmatrix.sync.aligned.m8n8.x4.shared.b16 {%0,%1,%2,%3}, [%4];"
                 : "=r"(r[0]), "=r"(r[1]), "=r"(r[2]), "=r"(r[3]) : "r"(addr));
}
__device__ __forceinline__ void ldsm4t(uint32_t* r, uint32_t addr) {
    asm volatile("ldmatrix.sync.aligned.m8n8.x4.trans.shared.b16 {%0,%1,%2,%3}, [%4];"
                 : "=r"(r[0]), "=r"(r[1]), "=r"(r[2]), "=r"(r[3]) : "r"(addr));
}

__device__ __forceinline__ void split2(float v, __half& h, __half& l) {
    h = __float2half_rn(v);
    l = __float2half_rn(v - __half2float(h));
}

__device__ __forceinline__ void cpa16(uint32_t dst, const void* src) {
    asm volatile("cp.async.cg.shared.global [%0], [%1], 16;"
                 :: "r"(dst), "l"(__cvta_generic_to_global(src)));
}
#define CPA_COMMIT() asm volatile("cp.async.commit_group;" ::: "memory")
#define CPA_WAIT0()  asm volatile("cp.async.wait_group 0;"  ::: "memory")

// =====================================================================
// Kernel 0: zero buffers + pre-split weights, one kernel.
// =====================================================================
__global__ void k_init(const float* __restrict__ w1,
                       const float* __restrict__ rank_w)
{
    const int blk = blockIdx.x;
    if (blk < 640) {
        const int i = blk * 256 + threadIdx.x;
        if (i < 131072) g_awin[i] = 0.f;
        else            g_att_acc[i - 131072] = 0.f;
    } else if (blk < 1152) {
        const int i = ((blk - 640) * 256 + threadIdx.x) * 4;
        const float4 v = *(const float4*)(w1 + i);
        __half h[4], l[4];
        split2(v.x, h[0], l[0]); split2(v.y, h[1], l[1]);
        split2(v.z, h[2], l[2]); split2(v.w, h[3], l[3]);
        *(uint2*)&g_w1h[i] = *(const uint2*)h;
        *(uint2*)&g_w1l[i] = *(const uint2*)l;
    } else {
        const int i = ((blk - 1152) * 256 + threadIdx.x) * 4;  // 128 blocks cover 131072
        const float4 v = *(const float4*)(rank_w + i);
        __half h[4], l[4];
        split2(v.x, h[0], l[0]); split2(v.y, h[1], l[1]);
        split2(v.z, h[2], l[2]); split2(v.w, h[3], l[3]);
        *(uint2*)&g_rwh[i] = *(const uint2*)h;
        *(uint2*)&g_rwl[i] = *(const uint2*)l;
    }
}

// =====================================================================
// Fused main kernel: bids [0,340) = conv1 body, [340,2388) = rank body.
// =====================================================================
#define ASTR 24                          // conv: halves per row (48B)
#define CV_PLB  (128 * ASTR * 2)         // conv: bytes per plane (6144)
#define RK_ASTR 72
#define RK_BSTR 40
#define RK_APLB (32 * RK_ASTR * 2)       // rank A plane bytes (4608)
#define RK_BPLB (64 * RK_BSTR * 2)       // rank B plane bytes (5120)
#define SMEM_MAIN 49152

__global__ __launch_bounds__(256, 2)
void k_main(const float* __restrict__ in, const float* __restrict__ b1)
{
    extern __shared__ __align__(16) char dyn[];
    const uint32_t dynB = smem_u32(dyn);
    const int tid = threadIdx.x;

    if (blockIdx.x < 340) {
        // ============================ conv1 body ============================
        const int mt = blockIdx.x % 85;
        const int nt = blockIdx.x / 85;

        const int lm = tid & 127;
        const int lh = tid >> 7;

        const int m  = mt * 128 + lm;
        const bool mv = (m < M1);
        const int ms = mv ? m : 0;
        const int bb = ms / 169;
        const int p  = ms % 169;
        const int yy = p / 13, xx = p % 13;
        const float* inb = in + (size_t)(bb * 8) * CIN * HWSZ + yy * 14 + xx;
        const __half* w1hp = g_w1h + (size_t)(nt * 128 + lm) * 1024 + lh * 8;
        const __half* w1lp = g_w1l + (size_t)(nt * 128 + lm) * 1024 + lh * 8;

        const uint32_t baseAh = dynB;
        const uint32_t baseAl = dynB + 2 * CV_PLB;
        const uint32_t baseBh = dynB + 4 * CV_PLB;
        const uint32_t baseBl = dynB + 6 * CV_PLB;
        const uint32_t rowOff = (uint32_t)(lm * ASTR + lh * 8) * 2u;
        const uint32_t stAh = baseAh + rowOff;
        const uint32_t stAl = baseAl + rowOff;
        const uint32_t stBh = baseBh + rowOff;
        const uint32_t stBl = baseBl + rowOff;

        const int w    = tid >> 5;
        const int lane = tid & 31;
        const int wm   = w & 3;
        const int wn   = w >> 2;
        const int am   = wm * 32;
        const int bn   = wn * 64;

        const int lr  = lane & 7;
        const int sel = lane >> 3;
        const int aRow  = (sel & 1) * 8 + lr;
        const int aByte = (sel >> 1) * 16;
        const int bRow  = (sel >> 1) * 8 + lr;
        const int bByte = (sel & 1) * 16;

        float acc[2][8][4];
#pragma unroll
        for (int i = 0; i < 2; i++)
#pragma unroll
            for (int j = 0; j < 8; j++)
#pragma unroll
                for (int c = 0; c < 4; c++) acc[i][j][c] = 0.f;

        float av[8];
        uint4 bhv, blv;

#define LOAD_REGS(ST) do {                                                \
        _Pragma("unroll")                                                 \
        for (int cc = 0; cc < 2; ++cc) {                                  \
            const int ch = (ST) * 4 + lh * 2 + cc;                        \
            const float* pA = inb + ((ch >> 5) * CIN + (ch & 31)) * HWSZ; \
            if (mv) { av[cc*4+0] = pA[0];  av[cc*4+1] = pA[1];            \
                      av[cc*4+2] = pA[14]; av[cc*4+3] = pA[15]; }         \
            else    { av[cc*4+0]=av[cc*4+1]=av[cc*4+2]=av[cc*4+3]=0.f; }  \
        }                                                                 \
        bhv = *(const uint4*)(w1hp + (ST) * 16);                          \
        blv = *(const uint4*)(w1lp + (ST) * 16);                          \
    } while (0)

#define STORE_REGS(BUF) do {                                              \
        __half h[8], l[8];                                                \
        _Pragma("unroll")                                                 \
        for (int q = 0; q < 8; ++q) split2(av[q], h[q], l[q]);            \
        asm volatile("st.shared.v4.b32 [%0], {%1,%2,%3,%4};" ::           \
            "r"(stAh + (BUF) * CV_PLB),                                   \
            "r"(*(const uint32_t*)&h[0]), "r"(*(const uint32_t*)&h[2]),   \
            "r"(*(const uint32_t*)&h[4]), "r"(*(const uint32_t*)&h[6]));  \
        asm volatile("st.shared.v4.b32 [%0], {%1,%2,%3,%4};" ::           \
            "r"(stAl + (BUF) * CV_PLB),                                   \
            "r"(*(const uint32_t*)&l[0]), "r"(*(const uint32_t*)&l[2]),   \
            "r"(*(const uint32_t*)&l[4]), "r"(*(const uint32_t*)&l[6]));  \
        asm volatile("st.shared.v4.b32 [%0], {%1,%2,%3,%4};" ::           \
            "r"(stBh + (BUF) * CV_PLB),                                   \
            "r"(bhv.x), "r"(bhv.y), "r"(bhv.z), "r"(bhv.w));              \
        asm volatile("st.shared.v4.b32 [%0], {%1,%2,%3,%4};" ::           \
            "r"(stBl + (BUF) * CV_PLB),                                   \
            "r"(blv.x), "r"(blv.y), "r"(blv.z), "r"(blv.w));              \
    } while (0)

        LOAD_REGS(0);
        STORE_REGS(0);
        __syncthreads();

        for (int st = 0; st < 64; ++st) {
            const int cur = st & 1;
            if (st + 1 < 64) LOAD_REGS(st + 1);

            uint32_t ah[2][4], al[2][4];
#pragma unroll
            for (int i = 0; i < 2; i++) {
                const uint32_t ro = (uint32_t)((am + i * 16 + aRow) * ASTR) * 2u + aByte;
                ldsm4(ah[i], baseAh + cur * CV_PLB + ro);
                ldsm4(al[i], baseAl + cur * CV_PLB + ro);
            }

#pragma unroll
            for (int jj = 0; jj < 4; ++jj) {
                const uint32_t ro = (uint32_t)((bn + jj * 16 + bRow) * ASTR) * 2u + bByte;
                uint32_t bh[4], bl[4];
                ldsm4(bh, baseBh + cur * CV_PLB + ro);
                ldsm4(bl, baseBl + cur * CV_PLB + ro);
#pragma unroll
                for (int t = 0; t < 2; ++t) {
                    const int j = jj * 2 + t;
#pragma unroll
                    for (int i = 0; i < 2; ++i) {
                        mma_f16(acc[i][j], ah[i], bh[t * 2], bh[t * 2 + 1]);  // hh
                        mma_f16(acc[i][j], ah[i], bl[t * 2], bl[t * 2 + 1]);  // hl
                        mma_f16(acc[i][j], al[i], bh[t * 2], bh[t * 2 + 1]);  // lh
                    }
                }
            }

            if (st + 1 < 64) STORE_REGS(cur ^ 1);
            __syncthreads();
        }

        // ---- fused epilogue: bias + relu + window sums -> g_awin atomics
        const int qr = lane >> 2;
        const int qc = lane & 3;
        const int b0 = (mt * 128) / 169;
#pragma unroll
        for (int j = 0; j < 8; j++) {
            const int nbase = nt * 128 + bn + j * 8 + qc * 2;
            const float bia0 = __ldg(b1 + nbase);
            const float bia1 = __ldg(b1 + nbase + 1);
#pragma unroll
            for (int z = 0; z < 2; z++) {
                const float bia = z ? bia1 : bia0;
                float w4[2][4] = {{0.f,0.f,0.f,0.f},{0.f,0.f,0.f,0.f}};
#pragma unroll
                for (int i = 0; i < 2; i++) {
#pragma unroll
                    for (int h = 0; h < 2; h++) {
                        const int mr = mt * 128 + am + i * 16 + qr + h * 8;
                        if (mr < M1) {
                            float v = acc[i][j][h * 2 + z] + bia;
                            v = v > 0.f ? v : 0.f;
                            const int bl2 = mr / 169 - b0;
                            const int pp  = mr % 169;
                            const int y   = pp / 13, x = pp - y * 13;
                            if (y < 12) { if (x < 12) w4[bl2][0] += v; if (x > 0) w4[bl2][1] += v; }
                            if (y > 0)  { if (x < 12) w4[bl2][2] += v; if (x > 0) w4[bl2][3] += v; }
                        }
                    }
                }
#pragma unroll
                for (int o = 4; o <= 16; o <<= 1)
#pragma unroll
                    for (int bl2 = 0; bl2 < 2; bl2++)
#pragma unroll
                        for (int t = 0; t < 4; t++)
                            w4[bl2][t] += __shfl_xor_sync(0xffffffffu, w4[bl2][t], o);
                if (qr == 0) {
                    const int n = nbase + z;
#pragma unroll
                    for (int bl2 = 0; bl2 < 2; bl2++) {
                        const int bg = b0 + bl2;
#pragma unroll
                        for (int t = 0; t < 4; t++)
                            if (w4[bl2][t] != 0.f)
                                atomicAdd(&g_awin[bg * 2048 + n * 4 + t], w4[bl2][t]);
                    }
                }
            }
        }
#undef LOAD_REGS
#undef STORE_REGS
    } else {
        // ============================ rank body ============================
        const int rid = blockIdx.x - 340;
        const int q = rid & 3;
        const int s = (rid >> 2) & 7;
        const int b = rid >> 5;
        const int hwb = q * 48;

        const float* img = in + (size_t)(b * 8 + s) * CIN * HWSZ;

        const int acr = tid >> 3;
        const int acg = (tid & 7) * 8;
        const int brr = tid >> 2;
        const int bcg = (tid & 3) * 8;
        const __half* whr = g_rwh + (size_t)(s * 64 + brr) * 256 + bcg;
        const __half* wlr = g_rwl + (size_t)(s * 64 + brr) * 256 + bcg;

        const uint32_t baseAh = dynB;
        const uint32_t baseAl = dynB + 2 * RK_APLB;
        const uint32_t baseBh = dynB + 4 * RK_APLB;
        const uint32_t baseBl = dynB + 4 * RK_APLB + 2 * RK_BPLB;
        const uint32_t stA_h = baseAh + (uint32_t)(acr * RK_ASTR + acg) * 2u;
        const uint32_t stA_l = baseAl + (uint32_t)(acr * RK_ASTR + acg) * 2u;
        const uint32_t stB_h = baseBh + (uint32_t)(brr * RK_BSTR + bcg) * 2u;
        const uint32_t stB_l = baseBl + (uint32_t)(brr * RK_BSTR + bcg) * 2u;

        const int w    = tid >> 5;
        const int lane = tid & 31;
        const int wm   = w & 3;
        const int wn   = w >> 2;
        const int lr   = lane & 7;
        const int sel  = lane >> 3;

        const uint32_t aOff = (uint32_t)((((sel >> 1) * 8 + lr) * RK_ASTR
                                         + wm * 16 + (sel & 1) * 8)) * 2u;
        const uint32_t bOff = (uint32_t)((wn * 32 + (sel >> 1) * 8 + lr) * RK_BSTR) * 2u
                              + (sel & 1) * 16;

        float acc[4][4];
#pragma unroll
        for (int j = 0; j < 4; j++)
#pragma unroll
            for (int c = 0; c < 4; c++) acc[j][c] = 0.f;

        float avv[8];

#define RK_LOAD_A(ST) do {                                                  \
        const float* ar = img + (size_t)((ST) * 32 + acr) * HWSZ + hwb + acg;\
        const int hw0 = hwb + acg;                                          \
        if (hw0 + 7 < HWSZ) {                                               \
            const float4 t0 = *(const float4*)ar;                           \
            const float4 t1 = *(const float4*)(ar + 4);                     \
            avv[0]=t0.x; avv[1]=t0.y; avv[2]=t0.z; avv[3]=t0.w;             \
            avv[4]=t1.x; avv[5]=t1.y; avv[6]=t1.z; avv[7]=t1.w;             \
        } else {                                                            \
            _Pragma("unroll")                                               \
            for (int k2 = 0; k2 < 8; ++k2)                                  \
                avv[k2] = (hw0 + k2 < HWSZ) ? ar[k2] : 0.f;                 \
        }                                                                   \
    } while (0)

#define RK_CPA_B(ST, BUF) do {                                              \
        cpa16(stB_h + (BUF) * RK_BPLB, whr + (ST) * 32);                    \
        cpa16(stB_l + (BUF) * RK_BPLB, wlr + (ST) * 32);                    \
        CPA_COMMIT();                                                       \
    } while (0)

#define RK_STORE_A(BUF) do {                                                \
        __half h[8], l[8];                                                  \
        _Pragma("unroll")                                                   \
        for (int k2 = 0; k2 < 8; ++k2) split2(avv[k2], h[k2], l[k2]);       \
        asm volatile("st.shared.v4.b32 [%0], {%1,%2,%3,%4};" ::             \
            "r"(stA_h + (BUF) * RK_APLB),                                   \
            "r"(*(const uint32_t*)&h[0]), "r"(*(const uint32_t*)&h[2]),     \
            "r"(*(const uint32_t*)&h[4]), "r"(*(const uint32_t*)&h[6]));    \
        asm volatile("st.shared.v4.b32 [%0], {%1,%2,%3,%4};" ::             \
            "r"(stA_l + (BUF) * RK_APLB),                                   \
            "r"(*(const uint32_t*)&l[0]), "r"(*(const uint32_t*)&l[2]),     \
            "r"(*(const uint32_t*)&l[4]), "r"(*(const uint32_t*)&l[6]));    \
    } while (0)

        RK_CPA_B(0, 0);
        RK_LOAD_A(0);
        RK_STORE_A(0);
        CPA_WAIT0();
        __syncthreads();

        for (int st = 0; st < 8; ++st) {
            const int cur = st & 1;
            if (st + 1 < 8) {
                RK_LOAD_A(st + 1);
                RK_CPA_B(st + 1, cur ^ 1);
            }

#pragma unroll
            for (int ks = 0; ks < 2; ++ks) {
                uint32_t ah[4], al[4];
                const uint32_t ao = cur * RK_APLB + (uint32_t)(ks * 16 * RK_ASTR) * 2u + aOff;
                ldsm4t(ah, baseAh + ao);
                ldsm4t(al, baseAl + ao);
#pragma unroll
                for (int jj = 0; jj < 2; ++jj) {
                    uint32_t bh[4], bl2[4];
                    const uint32_t bo = cur * RK_BPLB + (uint32_t)(jj * 16 * RK_BSTR) * 2u
                                        + ks * 32 + bOff;
                    ldsm4(bh, baseBh + bo);
                    ldsm4(bl2, baseBl + bo);
#pragma unroll
                    for (int t = 0; t < 2; ++t) {
                        const int jn = jj * 2 + t;
                        mma_f16(acc[jn], ah, bh[t * 2], bh[t * 2 + 1]);
                        mma_f16(acc[jn], ah, bl2[t * 2], bl2[t * 2 + 1]);
                        mma_f16(acc[jn], al, bh[t * 2], bh[t * 2 + 1]);
                    }
                }
            }

            if (st + 1 < 8) RK_STORE_A(cur ^ 1);
            CPA_WAIT0();
            __syncthreads();
        }

        const int g  = lane >> 2;
        const int tg = lane & 3;
#pragma unroll
        for (int j = 0; j < 4; j++) {
            const int r0 = wn * 32 + j * 8 + tg * 2;
#pragma unroll
            for (int h = 0; h < 2; h++) {
                const int hw = hwb + wm * 16 + g + h * 8;
                if (hw < HWSZ) {
                    g_xr[((size_t)(b * 64 + r0) * 8 + s) * HWSZ + hw]     = acc[j][h * 2 + 0];
                    g_xr[((size_t)(b * 64 + r0 + 1) * 8 + s) * HWSZ + hw] = acc[j][h * 2 + 1];
                }
            }
        }
#undef RK_LOAD_A
#undef RK_CPA_B
#undef RK_STORE_A
    }
}

// =====================================================================
// Kernel 3: conv2-as-GEMM on window sums. M=64, N=512, K=2048.
// =====================================================================
__global__ __launch_bounds__(256)
void k_gemm2(const float* __restrict__ w2)
{
    __shared__ __align__(16) float As[16][64];
    __shared__ __align__(16) float Bs[16][64];

    const int ot = blockIdx.x, ks = blockIdx.y;   // ot 0..7, ks 0..31
    const int tid = threadIdx.x;
    const int l = tid & 63, kg = tid >> 6;
    const int tm = tid >> 4, tn = tid & 15;

    float acc[4][4];
#pragma unroll
    for (int i = 0; i < 4; i++)
#pragma unroll
        for (int j = 0; j < 4; j++) acc[i][j] = 0.f;

    for (int it = 0; it < 4; ++it) {
        const int kb = ks * 64 + it * 16;
        const float4 av = *(const float4*)&g_awin[l * 2048 + kb + kg * 4];
        const float4 bv = *(const float4*)(w2 + (size_t)(ot * 64 + l) * 2048 + kb + kg * 4);
        As[kg * 4 + 0][l] = av.x; As[kg * 4 + 1][l] = av.y;
        As[kg * 4 + 2][l] = av.z; As[kg * 4 + 3][l] = av.w;
        Bs[kg * 4 + 0][l] = bv.x; Bs[kg * 4 + 1][l] = bv.y;
        Bs[kg * 4 + 2][l] = bv.z; Bs[kg * 4 + 3][l] = bv.w;
        __syncthreads();
#pragma unroll
        for (int kk = 0; kk < 16; ++kk) {
            float a[4], bbx[4];
            *(float4*)&a[0]   = *(const float4*)&As[kk][tm * 4];
            *(float4*)&bbx[0] = *(const float4*)&Bs[kk][tn * 4];
#pragma unroll
            for (int i = 0; i < 4; i++)
#pragma unroll
                for (int j = 0; j < 4; j++)
                    acc[i][j] = fmaf(a[i], bbx[j], acc[i][j]);
        }
        __syncthreads();
    }
#pragma unroll
    for (int i = 0; i < 4; i++)
#pragma unroll
        for (int j = 0; j < 4; j++)
            atomicAdd(&g_att_acc[(tm * 4 + i) * 512 + ot * 64 + tn * 4 + j], acc[i][j]);
}

// =====================================================================
// Kernel 4: pooled y per (b,r) — one warp per pair (4096 warps).
//   grid 512 x 256 threads (8 warps each).
// =====================================================================
__global__ __launch_bounds__(256)
void k_pool(const float* __restrict__ b2, const float* __restrict__ rank_b)
{
    const int tid = threadIdx.x, wid = tid >> 5, lane = tid & 31;
    const int pair = blockIdx.x * 8 + wid;      // 0..4095
    const int b = pair >> 6, r = pair & 63;

    float att[8]; int mi = 0; float best = -1e30f;
#pragma unroll
    for (int s = 0; s < 8; s++) {
        const float v = g_att_acc[b * 512 + s * 64 + r] * (1.f / 144.f)
                        + __ldg(b2 + s * 64 + r);
        const float a = 1.f / (1.f + expf(-v));
        att[s] = a;
        if (a > best) { best = a; mi = s; }
    }
    float rbv[8];
#pragma unroll
    for (int s = 0; s < 8; s++) rbv[s] = __ldg(rank_b + s * 64 + r) * att[s];

    const float* base = g_xr + (size_t)(b * 64 + r) * 8 * HWSZ;
    float sum = 0.f;
#pragma unroll
    for (int it = 0; it < 7; ++it) {          // 7*28 = 196; lane covers stride 32
        const int hw = it * 32 + lane;
        if (hw < HWSZ) {
            float tot = 0.f, piv = 0.f;
#pragma unroll
            for (int s = 0; s < 8; s++) {
                const float v = base[s * HWSZ + hw] * att[s] + rbv[s];
                tot += v;
                if (s == mi) piv = v;
            }
            sum += piv * (tot - piv);
        }
    }
#pragma unroll
    for (int o = 16; o; o >>= 1) sum += __shfl_down_sync(0xffffffffu, sum, o);
    if (lane == 0) g_pool[b * 64 + r] = sum * (1.f / (7.f * 196.f));
}

// =====================================================================
// Kernel 5: final linear. grid 64 x 512; pooled row staged in smem.
// =====================================================================
__global__ __launch_bounds__(512)
void k_lin(const float* __restrict__ lin_w, const float* __restrict__ lin_b,
           float* __restrict__ out)
{
    __shared__ float pooled[64];
    const int b = blockIdx.x, tid = threadIdx.x;
    if (tid < 64) pooled[tid] = g_pool[b * 64 + tid];
    __syncthreads();

    float a = lin_b[tid];
#pragma unroll
    for (int r = 0; r < 64; r++)
        a = fmaf(pooled[r], lin_w[tid * 64 + r], a);
    out[b * 512 + tid] = a;
}

// =====================================================================
extern "C" void kernel_launch(void* const* d_in, const int* in_sizes, int n_in,
                              void* d_out, int out_size)
{
    const float* in = (const float*)d_in[0];
    const float* w1 = (const float*)d_in[1];
    const float* b1 = (const float*)d_in[2];
    const float* w2 = (const float*)d_in[3];
    const float* b2 = (const float*)d_in[4];
    const float* rw = (const float*)d_in[5];
    const float* rb = (const float*)d_in[6];
    const float* lw = (const float*)d_in[7];
    const float* lb = (const float*)d_in[8];
    float* out = (float*)d_out;

    k_init <<<1280, 256>>>(w1, rw);                 // zero + weight split
    k_main <<<2388, 256, SMEM_MAIN>>>(in, b1);      // conv1 + rank fused grid
    k_gemm2<<<dim3(8, 32), 256>>>(w2);
    k_pool <<<512, 256>>>(b2, rb);
    k_lin  <<<64, 512>>>(lw, lb, out);
}